// round 1
// baseline (speedup 1.0000x reference)
#include <cuda_runtime.h>
#include <cuda_bf16.h>
#include <mma.h>

using namespace nvcuda;

// Problem dims
#define B_  4
#define S_  4096
#define D_  2048
#define T_  1024
#define H_  16
#define HD_ 128
#define F_  8192
#define M_  (B_*T_)          // 4096 total selected rows

// ---------------- device scratch (allowed: __device__ globals) ----------------
#define DEVBUF(type, name, count) __device__ __align__(256) type name[count]

DEVBUF(__nv_bfloat16, g_wq_b, D_*D_);
DEVBUF(__nv_bfloat16, g_wk_b, D_*D_);
DEVBUF(__nv_bfloat16, g_wv_b, D_*D_);
DEVBUF(__nv_bfloat16, g_wo_b, D_*D_);
DEVBUF(__nv_bfloat16, g_w1_b, D_*F_);
DEVBUF(__nv_bfloat16, g_w3_b, D_*F_);
DEVBUF(__nv_bfloat16, g_w2_b, F_*D_);

DEVBUF(float, g_logits, B_*S_);
DEVBUF(int,   g_sel,    B_*T_);
DEVBUF(int,   g_pos,    B_*S_);
DEVBUF(float, g_rw,     B_*T_);

DEVBUF(float,         g_fx,  M_*D_);     // gathered x (fp32, for residual)
DEVBUF(__nv_bfloat16, g_h,   M_*D_);     // rmsnorm1 out (bf16)
DEVBUF(float,         g_q,   M_*D_);
DEVBUF(float,         g_k,   M_*D_);
DEVBUF(float,         g_v,   M_*D_);
DEVBUF(__nv_bfloat16, g_qb,  M_*D_);     // [b,h,t,hd] after rope
DEVBUF(__nv_bfloat16, g_kb,  M_*D_);
DEVBUF(__nv_bfloat16, g_vb,  M_*D_);
DEVBUF(float,         g_scores, B_*H_*T_*T_);   // 256 MB
DEVBUF(__nv_bfloat16, g_probs,  B_*H_*T_*T_);   // 128 MB
DEVBUF(float,         g_o,   M_*D_);     // [b,h,t,hd]
DEVBUF(__nv_bfloat16, g_ob,  M_*D_);     // [b,t,d]
DEVBUF(float,         g_x1,  M_*D_);     // x + attn
DEVBUF(__nv_bfloat16, g_h2,  M_*D_);     // rmsnorm2 out
DEVBUF(float,         g_u,   M_*F_);     // h2@w1
DEVBUF(float,         g_g,   M_*F_);     // h2@w3
DEVBUF(__nv_bfloat16, g_act, M_*F_);     // silu(u)*g
DEVBUF(float,         g_y,   M_*D_);     // attn proj, then ffn out

// ---------------- generic bf16 WMMA GEMM ----------------
// C[M,N] fp32 = A[M,K] * B   (BT=0: B is [K,N] row-major; BT=1: B is [N,K] row-major -> C=A*B^T)
#define BM 128
#define BN 128
#define BK 32
#define SA_LD 40
#define SB_LD 136

template<int BT>
__global__ void __launch_bounds__(256) gemm_kernel(
    const __nv_bfloat16* __restrict__ A, const __nv_bfloat16* __restrict__ Bm,
    float* __restrict__ C, int M, int N, int K, int lda, int ldb, int ldc,
    long long sA, long long sB, long long sC)
{
    __shared__ __nv_bfloat16 As[BM*SA_LD];
    __shared__ __nv_bfloat16 Bs[BK*SB_LD];
    int z = blockIdx.z;
    A  += z*sA; Bm += z*sB; C += z*sC;
    int bm = blockIdx.y*BM, bn = blockIdx.x*BN;
    int tid = threadIdx.x;
    int warp = tid >> 5;
    int wm = (warp >> 1) * 32;   // 0..96
    int wn = (warp & 1) * 64;    // 0,64

    wmma::fragment<wmma::accumulator,16,16,16,float> acc[2][4];
    #pragma unroll
    for (int i=0;i<2;i++)
        #pragma unroll
        for (int j=0;j<4;j++) wmma::fill_fragment(acc[i][j], 0.f);

    for (int k0 = 0; k0 < K; k0 += BK) {
        #pragma unroll
        for (int l=0;l<2;l++){
            int idx = tid + l*256;
            int r = idx >> 2, c = (idx & 3) * 8;
            uint4 vA = *reinterpret_cast<const uint4*>(A + (long long)(bm+r)*lda + k0 + c);
            *reinterpret_cast<uint4*>(&As[r*SA_LD + c]) = vA;
        }
        if (BT == 0) {
            #pragma unroll
            for (int l=0;l<2;l++){
                int idx = tid + l*256;
                int r = idx >> 4, c = (idx & 15) * 8;
                uint4 vB = *reinterpret_cast<const uint4*>(Bm + (long long)(k0+r)*ldb + bn + c);
                *reinterpret_cast<uint4*>(&Bs[r*SB_LD + c]) = vB;
            }
        } else {
            #pragma unroll
            for (int l=0;l<2;l++){
                int idx = tid + l*256;
                int n = idx >> 2, c = (idx & 3) * 8;
                __nv_bfloat16 tmp[8];
                *reinterpret_cast<uint4*>(tmp) =
                    *reinterpret_cast<const uint4*>(Bm + (long long)(bn+n)*ldb + k0 + c);
                #pragma unroll
                for (int j=0;j<8;j++) Bs[(c+j)*SB_LD + n] = tmp[j];
            }
        }
        __syncthreads();
        #pragma unroll
        for (int kk=0; kk<BK; kk+=16){
            wmma::fragment<wmma::matrix_a,16,16,16,__nv_bfloat16,wmma::row_major> af[2];
            wmma::fragment<wmma::matrix_b,16,16,16,__nv_bfloat16,wmma::row_major> bfg[4];
            #pragma unroll
            for (int i=0;i<2;i++) wmma::load_matrix_sync(af[i], &As[(wm+i*16)*SA_LD + kk], SA_LD);
            #pragma unroll
            for (int j=0;j<4;j++) wmma::load_matrix_sync(bfg[j], &Bs[kk*SB_LD + wn + j*16], SB_LD);
            #pragma unroll
            for (int i=0;i<2;i++)
                #pragma unroll
                for (int j=0;j<4;j++) wmma::mma_sync(acc[i][j], af[i], bfg[j], acc[i][j]);
        }
        __syncthreads();
    }
    #pragma unroll
    for (int i=0;i<2;i++)
        #pragma unroll
        for (int j=0;j<4;j++)
            wmma::store_matrix_sync(C + (long long)(bm+wm+i*16)*ldc + bn+wn+j*16,
                                    acc[i][j], ldc, wmma::mem_row_major);
}

// ---------------- elementwise / reduction kernels ----------------

__global__ void cvt_kernel(const float* __restrict__ s, __nv_bfloat16* __restrict__ d, int n4){
    for (int i = blockIdx.x*blockDim.x + threadIdx.x; i < n4; i += gridDim.x*blockDim.x){
        float4 v = reinterpret_cast<const float4*>(s)[i];
        __nv_bfloat162* o = reinterpret_cast<__nv_bfloat162*>(d) + (long long)i*2;
        o[0] = __floats2bfloat162_rn(v.x, v.y);
        o[1] = __floats2bfloat162_rn(v.z, v.w);
    }
}

__global__ void __launch_bounds__(256) router_kernel(const float* __restrict__ x,
                                                     const float* __restrict__ wr){
    int row = blockIdx.x*8 + (threadIdx.x >> 5);
    int lane = threadIdx.x & 31;
    const float* xr = x + (long long)row * D_;
    float s = 0.f;
    #pragma unroll 8
    for (int i = lane; i < D_; i += 32) s += xr[i] * wr[i];
    #pragma unroll
    for (int o=16;o;o>>=1) s += __shfl_xor_sync(0xffffffffu, s, o);
    if (!lane) g_logits[row] = s;
}

__global__ void __launch_bounds__(1024) topk_kernel(){
    __shared__ float sv[S_];
    __shared__ int   scn[1024];
    __shared__ float selv[T_];
    __shared__ float red[1024];
    int b = blockIdx.x, tid = threadIdx.x;
    for (int i = tid; i < S_; i += 1024) sv[i] = g_logits[b*S_ + i];
    __syncthreads();
    int base_i = tid*4;
    float v[4]; int rank[4] = {0,0,0,0};
    #pragma unroll
    for (int e=0;e<4;e++) v[e] = sv[base_i+e];
    for (int j=0;j<S_;j++){
        float vj = sv[j];
        #pragma unroll
        for (int e=0;e<4;e++)
            rank[e] += (vj > v[e]) || (vj == v[e] && j < base_i+e);
    }
    int flag[4]; int cnt = 0;
    #pragma unroll
    for (int e=0;e<4;e++){ flag[e] = rank[e] < T_; cnt += flag[e]; }
    scn[tid] = cnt; __syncthreads();
    for (int off=1; off<1024; off<<=1){
        int t = 0;
        if (tid >= off) t = scn[tid-off];
        __syncthreads();
        scn[tid] += t;
        __syncthreads();
    }
    int pos = scn[tid] - cnt;
    #pragma unroll
    for (int e=0;e<4;e++){
        int i = base_i + e;
        int p = -1;
        if (flag[e]){ p = pos++; g_sel[b*T_+p] = i; selv[p] = v[e]; }
        g_pos[b*S_ + i] = p;
    }
    __syncthreads();
    float sval = selv[tid];
    red[tid] = sval; __syncthreads();
    for (int off=512; off; off>>=1){ if (tid < off) red[tid] = fmaxf(red[tid], red[tid+off]); __syncthreads(); }
    float mx = red[0]; __syncthreads();
    float ex = __expf(sval - mx);
    red[tid] = ex; __syncthreads();
    for (int off=512; off; off>>=1){ if (tid < off) red[tid] += red[tid+off]; __syncthreads(); }
    g_rw[b*T_ + tid] = ex / red[0];
}

__device__ __forceinline__ float block_sum_256(float v, float* sh){
    #pragma unroll
    for (int o=16;o;o>>=1) v += __shfl_xor_sync(0xffffffffu, v, o);
    if ((threadIdx.x & 31) == 0) sh[threadIdx.x >> 5] = v;
    __syncthreads();
    if (threadIdx.x == 0){ float t=0; for (int w=0;w<8;w++) t += sh[w]; sh[0] = t; }
    __syncthreads();
    float r = sh[0];
    __syncthreads();
    return r;
}

__global__ void __launch_bounds__(256) gather_rms_kernel(const float* __restrict__ x,
                                                         const float* __restrict__ g1){
    __shared__ float sh[8];
    int bt = blockIdx.x;
    int b = bt >> 10;
    int s = g_sel[bt];
    const float* xr = x + ((long long)b*S_ + s) * D_;
    float vals[8]; float ss = 0.f;
    #pragma unroll
    for (int e=0;e<8;e++){ float val = xr[threadIdx.x + e*256]; vals[e] = val; ss += val*val; }
    float tot = block_sum_256(ss, sh);
    float inv = rsqrtf(tot / D_ + 1e-6f);
    long long base = (long long)bt * D_;
    #pragma unroll
    for (int e=0;e<8;e++){
        int d = threadIdx.x + e*256;
        g_fx[base+d] = vals[e];
        g_h[base+d]  = __float2bfloat16(vals[e] * inv * g1[d]);
    }
}

__global__ void __launch_bounds__(128) rope_pack_kernel(const float* __restrict__ f){
    int idx = blockIdx.x;
    int t  = idx & (T_-1);
    int bh = idx >> 10;
    int h  = bh & (H_-1);
    int b  = bh >> 4;
    int d  = threadIdx.x;
    long long src = ((long long)(b*T_ + t)) * D_ + h*HD_;
    long long dst = ((long long)(b*H_ + h) * T_ + t) * HD_ + d;
    float qv = g_q[src+d], kv = g_k[src+d], vv = g_v[src+d];
    float qo, ko;
    if (d < 64){
        float c = f[(t*64 + d)*2], sn = f[(t*64 + d)*2 + 1];
        qo = qv*c - g_q[src+d+64]*sn;
        ko = kv*c - g_k[src+d+64]*sn;
    } else {
        int j = d - 64;
        float c = f[(t*64 + j)*2], sn = f[(t*64 + j)*2 + 1];
        qo = g_q[src+j]*sn + qv*c;
        ko = g_k[src+j]*sn + kv*c;
    }
    g_qb[dst] = __float2bfloat16(qo);
    g_kb[dst] = __float2bfloat16(ko);
    g_vb[dst] = __float2bfloat16(vv);
}

__global__ void __launch_bounds__(256) softmax_kernel(){
    __shared__ float shw[8];
    __shared__ float res;
    long long row = blockIdx.x;
    const float* sr = g_scores + row * T_;
    __nv_bfloat16* pr = g_probs + row * T_;
    float v[4]; float mx = -1e30f;
    #pragma unroll
    for (int e=0;e<4;e++){ v[e] = sr[threadIdx.x + e*256] * 0.08838834764831845f; mx = fmaxf(mx, v[e]); }
    #pragma unroll
    for (int o=16;o;o>>=1) mx = fmaxf(mx, __shfl_xor_sync(0xffffffffu, mx, o));
    if ((threadIdx.x & 31) == 0) shw[threadIdx.x >> 5] = mx;
    __syncthreads();
    if (threadIdx.x == 0){ float t = shw[0]; for (int w=1;w<8;w++) t = fmaxf(t, shw[w]); res = t; }
    __syncthreads();
    mx = res;
    __syncthreads();
    float ex[4]; float sum = 0.f;
    #pragma unroll
    for (int e=0;e<4;e++){ ex[e] = __expf(v[e] - mx); sum += ex[e]; }
    #pragma unroll
    for (int o=16;o;o>>=1) sum += __shfl_xor_sync(0xffffffffu, sum, o);
    if ((threadIdx.x & 31) == 0) shw[threadIdx.x >> 5] = sum;
    __syncthreads();
    if (threadIdx.x == 0){ float t=0; for (int w=0;w<8;w++) t += shw[w]; res = t; }
    __syncthreads();
    float rinv = __frcp_rn(res);
    #pragma unroll
    for (int e=0;e<4;e++) pr[threadIdx.x + e*256] = __float2bfloat16(ex[e] * rinv);
}

__global__ void __launch_bounds__(128) perm_o_kernel(){
    int idx = blockIdx.x;
    int t  = idx & (T_-1);
    int bh = idx >> 10;
    int h  = bh & (H_-1);
    int b  = bh >> 4;
    int d  = threadIdx.x;
    g_ob[((long long)(b*T_ + t)) * D_ + h*HD_ + d] =
        __float2bfloat16(g_o[((long long)(b*H_ + h) * T_ + t) * HD_ + d]);
}

__global__ void __launch_bounds__(256) resid_rms_kernel(const float* __restrict__ g2){
    __shared__ float sh[8];
    long long base = (long long)blockIdx.x * D_;
    float vals[8]; float ss = 0.f;
    #pragma unroll
    for (int e=0;e<8;e++){
        int d = threadIdx.x + e*256;
        float val = g_fx[base+d] + g_y[base+d];
        vals[e] = val; ss += val*val;
    }
    float tot = block_sum_256(ss, sh);
    float inv = rsqrtf(tot / D_ + 1e-6f);
    #pragma unroll
    for (int e=0;e<8;e++){
        int d = threadIdx.x + e*256;
        g_x1[base+d] = vals[e];
        g_h2[base+d] = __float2bfloat16(vals[e] * inv * g2[d]);
    }
}

__global__ void act_kernel(){
    const int n4 = M_*F_/4;
    for (int i = blockIdx.x*blockDim.x + threadIdx.x; i < n4; i += gridDim.x*blockDim.x){
        float4 u = reinterpret_cast<const float4*>(g_u)[i];
        float4 g = reinterpret_cast<const float4*>(g_g)[i];
        float a0 = __fdividef(u.x, 1.f + __expf(-u.x)) * g.x;
        float a1 = __fdividef(u.y, 1.f + __expf(-u.y)) * g.y;
        float a2 = __fdividef(u.z, 1.f + __expf(-u.z)) * g.z;
        float a3 = __fdividef(u.w, 1.f + __expf(-u.w)) * g.w;
        __nv_bfloat162* o = reinterpret_cast<__nv_bfloat162*>(g_act) + (long long)i*2;
        o[0] = __floats2bfloat162_rn(a0, a1);
        o[1] = __floats2bfloat162_rn(a2, a3);
    }
}

__global__ void __launch_bounds__(256) final_kernel(const float* __restrict__ x,
                                                    float* __restrict__ out){
    int bs = blockIdx.x;
    int b = bs >> 12;                 // S_ = 4096
    int pos = g_pos[bs];
    long long rb = (long long)bs * D_;
    if (pos < 0){
        #pragma unroll
        for (int e=0;e<2;e++){
            int i = threadIdx.x + e*256;
            reinterpret_cast<float4*>(out + rb)[i] =
                reinterpret_cast<const float4*>(x + rb)[i];
        }
    } else {
        float w = g_rw[b*T_ + pos];
        long long ob = ((long long)b*T_ + pos) * D_;
        #pragma unroll
        for (int e=0;e<8;e++){
            int d = threadIdx.x + e*256;
            out[rb+d] = x[rb+d] + w * (g_x1[ob+d] + g_y[ob+d]);
        }
    }
}

// ---------------- host orchestration ----------------
#define GETP(sym_) ([&]{ void* p_ = nullptr; cudaGetSymbolAddress(&p_, sym_); return p_; }())

extern "C" void kernel_launch(void* const* d_in, const int* in_sizes, int n_in,
                              void* d_out, int out_size)
{
    const float* x     = (const float*)d_in[0];
    const float* freqs = (const float*)d_in[2];
    const float* wr    = (const float*)d_in[3];
    const float* g1    = (const float*)d_in[4];
    const float* wq    = (const float*)d_in[5];
    const float* wk    = (const float*)d_in[6];
    const float* wv    = (const float*)d_in[7];
    const float* wo    = (const float*)d_in[8];
    const float* g2    = (const float*)d_in[9];
    const float* w1    = (const float*)d_in[10];
    const float* w3    = (const float*)d_in[11];
    const float* w2    = (const float*)d_in[12];
    float* out = (float*)d_out;

    __nv_bfloat16* p_wq = (__nv_bfloat16*)GETP(g_wq_b);
    __nv_bfloat16* p_wk = (__nv_bfloat16*)GETP(g_wk_b);
    __nv_bfloat16* p_wv = (__nv_bfloat16*)GETP(g_wv_b);
    __nv_bfloat16* p_wo = (__nv_bfloat16*)GETP(g_wo_b);
    __nv_bfloat16* p_w1 = (__nv_bfloat16*)GETP(g_w1_b);
    __nv_bfloat16* p_w3 = (__nv_bfloat16*)GETP(g_w3_b);
    __nv_bfloat16* p_w2 = (__nv_bfloat16*)GETP(g_w2_b);
    __nv_bfloat16* p_h  = (__nv_bfloat16*)GETP(g_h);
    __nv_bfloat16* p_qb = (__nv_bfloat16*)GETP(g_qb);
    __nv_bfloat16* p_kb = (__nv_bfloat16*)GETP(g_kb);
    __nv_bfloat16* p_vb = (__nv_bfloat16*)GETP(g_vb);
    __nv_bfloat16* p_pr = (__nv_bfloat16*)GETP(g_probs);
    __nv_bfloat16* p_ob = (__nv_bfloat16*)GETP(g_ob);
    __nv_bfloat16* p_h2 = (__nv_bfloat16*)GETP(g_h2);
    __nv_bfloat16* p_ac = (__nv_bfloat16*)GETP(g_act);
    float* p_q  = (float*)GETP(g_q);
    float* p_k  = (float*)GETP(g_k);
    float* p_v  = (float*)GETP(g_v);
    float* p_sc = (float*)GETP(g_scores);
    float* p_o  = (float*)GETP(g_o);
    float* p_u  = (float*)GETP(g_u);
    float* p_g  = (float*)GETP(g_g);
    float* p_y  = (float*)GETP(g_y);

    // 1) weight conversions fp32 -> bf16
    cvt_kernel<<<2048,256>>>(wq, p_wq, D_*D_/4);
    cvt_kernel<<<2048,256>>>(wk, p_wk, D_*D_/4);
    cvt_kernel<<<2048,256>>>(wv, p_wv, D_*D_/4);
    cvt_kernel<<<2048,256>>>(wo, p_wo, D_*D_/4);
    cvt_kernel<<<4096,256>>>(w1, p_w1, D_*F_/4);
    cvt_kernel<<<4096,256>>>(w3, p_w3, D_*F_/4);
    cvt_kernel<<<4096,256>>>(w2, p_w2, F_*D_/4);

    // 2) router + exact top-k (rank counting, stable by index) + softmax weights
    router_kernel<<<B_*S_/8, 256>>>(x, wr);
    topk_kernel<<<B_, 1024>>>();

    // 3) gather + rmsnorm1
    gather_rms_kernel<<<M_, 256>>>(x, g1);

    // 4) QKV GEMMs: [4096,2048] x [2048,2048]
    gemm_kernel<0><<<dim3(D_/BN, M_/BM, 1), 256>>>(p_h, p_wq, p_q, M_, D_, D_, D_, D_, D_, 0,0,0);
    gemm_kernel<0><<<dim3(D_/BN, M_/BM, 1), 256>>>(p_h, p_wk, p_k, M_, D_, D_, D_, D_, D_, 0,0,0);
    gemm_kernel<0><<<dim3(D_/BN, M_/BM, 1), 256>>>(p_h, p_wv, p_v, M_, D_, D_, D_, D_, D_, 0,0,0);

    // 5) RoPE + pack to [b,h,t,hd] bf16
    rope_pack_kernel<<<B_*H_*T_, 128>>>(freqs);

    // 6) scores = Q K^T per (b,h): batched NT GEMM
    gemm_kernel<1><<<dim3(T_/BN, T_/BM, B_*H_), 256>>>(p_qb, p_kb, p_sc,
        T_, T_, HD_, HD_, HD_, T_, (long long)T_*HD_, (long long)T_*HD_, (long long)T_*T_);

    // 7) softmax -> bf16 probs
    softmax_kernel<<<B_*H_*T_, 256>>>();

    // 8) O = P V per (b,h)
    gemm_kernel<0><<<dim3(HD_/BN ? HD_/BN : 1, T_/BM, B_*H_), 256>>>(p_pr, p_vb, p_o,
        T_, HD_, T_, T_, HD_, HD_, (long long)T_*T_, (long long)T_*HD_, (long long)T_*HD_);

    // 9) permute o to [b,t,d] bf16, project with wo -> g_y
    perm_o_kernel<<<B_*H_*T_, 128>>>();
    gemm_kernel<0><<<dim3(D_/BN, M_/BM, 1), 256>>>(p_ob, p_wo, p_y, M_, D_, D_, D_, D_, D_, 0,0,0);

    // 10) residual + rmsnorm2
    resid_rms_kernel<<<M_, 256>>>(g2);

    // 11) FFN
    gemm_kernel<0><<<dim3(F_/BN, M_/BM, 1), 256>>>(p_h2, p_w1, p_u, M_, F_, D_, D_, F_, F_, 0,0,0);
    gemm_kernel<0><<<dim3(F_/BN, M_/BM, 1), 256>>>(p_h2, p_w3, p_g, M_, F_, D_, D_, F_, F_, 0,0,0);
    act_kernel<<<8192, 256>>>();
    gemm_kernel<0><<<dim3(D_/BN, M_/BM, 1), 256>>>(p_ac, p_w2, p_y, M_, D_, F_, F_, D_, D_, 0,0,0);

    // 12) scatter-add final output
    final_kernel<<<B_*S_, 256>>>(x, out);
}

// round 3
// speedup vs baseline: 1.1451x; 1.1451x over previous
#include <cuda_runtime.h>
#include <cuda_bf16.h>
#include <mma.h>
#include <cstdint>

using namespace nvcuda;

// Problem dims
#define B_  4
#define S_  4096
#define D_  2048
#define T_  1024
#define H_  16
#define HD_ 128
#define F_  8192
#define M_  (B_*T_)

// ---------------- device scratch ----------------
#define DEVBUF(type, name, count) __device__ __align__(256) type name[count]

DEVBUF(__nv_bfloat16, g_wq_b, D_*D_);
DEVBUF(__nv_bfloat16, g_wk_b, D_*D_);
DEVBUF(__nv_bfloat16, g_wv_b, D_*D_);
DEVBUF(__nv_bfloat16, g_wo_b, D_*D_);
DEVBUF(__nv_bfloat16, g_w1_b, D_*F_);
DEVBUF(__nv_bfloat16, g_w3_b, D_*F_);
DEVBUF(__nv_bfloat16, g_w2_b, F_*D_);

DEVBUF(float, g_logits, B_*S_);
DEVBUF(int,   g_sel,    B_*T_);
DEVBUF(int,   g_pos,    B_*S_);
DEVBUF(float, g_rw,     B_*T_);

DEVBUF(float,         g_fx,  M_*D_);
DEVBUF(__nv_bfloat16, g_h,   M_*D_);
DEVBUF(float,         g_q,   M_*D_);
DEVBUF(float,         g_k,   M_*D_);
DEVBUF(float,         g_v,   M_*D_);
DEVBUF(__nv_bfloat16, g_qb,  M_*D_);     // [b,h,t,hd]
DEVBUF(__nv_bfloat16, g_kb,  M_*D_);
DEVBUF(__nv_bfloat16, g_vb,  M_*D_);
DEVBUF(float,         g_scores, (long long)B_*H_*T_*T_);
DEVBUF(__nv_bfloat16, g_probs,  (long long)B_*H_*T_*T_);
DEVBUF(float,         g_o,   M_*D_);
DEVBUF(__nv_bfloat16, g_ob,  M_*D_);
DEVBUF(float,         g_x1,  M_*D_);
DEVBUF(__nv_bfloat16, g_h2,  M_*D_);
DEVBUF(float,         g_u,   M_*F_);
DEVBUF(float,         g_g,   M_*F_);
DEVBUF(__nv_bfloat16, g_act, M_*F_);
DEVBUF(float,         g_y,   M_*D_);

// ---------------- pipelined WMMA GEMM ----------------
// C[M,N] fp32 = A[M,K](row) * B  ; BT=0: B[K,N] row-major ; BT=1: B[N,K] row-major (C = A B^T)
// CTA tile 128x128, BK=64, 2-stage cp.async double buffer, 8 warps of 32x64.

#define BM 128
#define BN 128
#define BK 64
#define SA_STRIDE 72            // elems (144 B rows)
#define SB0_STRIDE 136          // elems (272 B rows), BT=0 tile is [64][128]
#define SB1_STRIDE 72           // BT=1 tile is [128][64]
#define A_TILE_B  (BM*SA_STRIDE*2)      // 18432
#define B_TILE_B  18432                 // max of both B tile sizes
#define GEMM_SMEM (2*A_TILE_B + 2*B_TILE_B)   // 73728

__device__ __forceinline__ uint32_t smem_u32(const void* p){
    uint32_t a;
    asm("{ .reg .u64 t; cvta.to.shared.u64 t, %1; cvt.u32.u64 %0, t; }" : "=r"(a) : "l"(p));
    return a;
}
__device__ __forceinline__ void cpasync16(uint32_t dst, const void* src){
    asm volatile("cp.async.cg.shared.global [%0], [%1], 16;" :: "r"(dst), "l"(src));
}

// A / BT1 tile: 128 rows x 64 cols bf16
__device__ __forceinline__ void ld_tile_128x64(const __nv_bfloat16* g, int ld, char* s, int tid){
    #pragma unroll
    for (int i = 0; i < 4; i++){
        int ch = tid + i*256;
        int r = ch >> 3, c = ch & 7;
        cpasync16(smem_u32(s + r*144 + c*16), (const char*)(g + (long long)r*ld) + c*16);
    }
}
// BT0 tile: 64 rows x 128 cols bf16
__device__ __forceinline__ void ld_tile_64x128(const __nv_bfloat16* g, int ld, char* s, int tid){
    #pragma unroll
    for (int i = 0; i < 4; i++){
        int ch = tid + i*256;
        int r = ch >> 4, c = ch & 15;
        cpasync16(smem_u32(s + r*272 + c*16), (const char*)(g + (long long)r*ld) + c*16);
    }
}

template<int BT>
__global__ void __launch_bounds__(256, 2) gemm2(
    const __nv_bfloat16* __restrict__ A, const __nv_bfloat16* __restrict__ Bm,
    float* __restrict__ C, int K, int lda, int ldb, int ldc,
    long long sA, long long sB, long long sC)
{
    extern __shared__ char smem[];
    char* As[2] = { smem, smem + A_TILE_B };
    char* Bs[2] = { smem + 2*A_TILE_B, smem + 2*A_TILE_B + B_TILE_B };

    int tid = threadIdx.x, warp = tid >> 5;
    int z = blockIdx.z;
    const __nv_bfloat16* Ab = A + (long long)z*sA + (long long)blockIdx.y*BM*lda;
    const __nv_bfloat16* Bb = Bm + (long long)z*sB;
    float* Cb = C + (long long)z*sC;

    int wm = (warp & 3) * 32;
    int wn = (warp >> 2) * 64;

    wmma::fragment<wmma::accumulator,16,16,16,float> acc[2][4];
    #pragma unroll
    for (int i=0;i<2;i++)
        #pragma unroll
        for (int j=0;j<4;j++) wmma::fill_fragment(acc[i][j], 0.f);

    const int NS = K >> 6;

    // preload stage 0
    ld_tile_128x64(Ab, lda, As[0], tid);
    if (BT == 0) ld_tile_64x128(Bb + (long long)0*ldb + blockIdx.x*BN, ldb, Bs[0], tid);
    else         ld_tile_128x64(Bb + (long long)blockIdx.x*BN*ldb, ldb, Bs[0], tid);
    asm volatile("cp.async.commit_group;" ::: "memory");

    for (int s = 0; s < NS; s++){
        int cur = s & 1;
        if (s + 1 < NS){
            int nxt = cur ^ 1;
            int k0 = (s+1)*BK;
            ld_tile_128x64(Ab + k0, lda, As[nxt], tid);
            if (BT == 0) ld_tile_64x128(Bb + (long long)k0*ldb + blockIdx.x*BN, ldb, Bs[nxt], tid);
            else         ld_tile_128x64(Bb + (long long)blockIdx.x*BN*ldb + k0, ldb, Bs[nxt], tid);
            asm volatile("cp.async.commit_group;" ::: "memory");
            asm volatile("cp.async.wait_group 1;" ::: "memory");
        } else {
            asm volatile("cp.async.wait_group 0;" ::: "memory");
        }
        __syncthreads();

        const __nv_bfloat16* as = (const __nv_bfloat16*)As[cur];
        const __nv_bfloat16* bs = (const __nv_bfloat16*)Bs[cur];
        #pragma unroll
        for (int kk = 0; kk < BK; kk += 16){
            wmma::fragment<wmma::matrix_a,16,16,16,__nv_bfloat16,wmma::row_major> af[2];
            #pragma unroll
            for (int i=0;i<2;i++)
                wmma::load_matrix_sync(af[i], as + (wm + i*16)*SA_STRIDE + kk, SA_STRIDE);
            if (BT == 0){
                wmma::fragment<wmma::matrix_b,16,16,16,__nv_bfloat16,wmma::row_major> bf[4];
                #pragma unroll
                for (int j=0;j<4;j++)
                    wmma::load_matrix_sync(bf[j], bs + kk*SB0_STRIDE + wn + j*16, SB0_STRIDE);
                #pragma unroll
                for (int i=0;i<2;i++)
                    #pragma unroll
                    for (int j=0;j<4;j++) wmma::mma_sync(acc[i][j], af[i], bf[j], acc[i][j]);
            } else {
                wmma::fragment<wmma::matrix_b,16,16,16,__nv_bfloat16,wmma::col_major> bf[4];
                #pragma unroll
                for (int j=0;j<4;j++)
                    wmma::load_matrix_sync(bf[j], bs + (wn + j*16)*SB1_STRIDE + kk, SB1_STRIDE);
                #pragma unroll
                for (int i=0;i<2;i++)
                    #pragma unroll
                    for (int j=0;j<4;j++) wmma::mma_sync(acc[i][j], af[i], bf[j], acc[i][j]);
            }
        }
        __syncthreads();
    }

    #pragma unroll
    for (int i=0;i<2;i++)
        #pragma unroll
        for (int j=0;j<4;j++)
            wmma::store_matrix_sync(Cb + (long long)(blockIdx.y*BM + wm + i*16)*ldc
                                       + blockIdx.x*BN + wn + j*16,
                                    acc[i][j], ldc, wmma::mem_row_major);
}

// ---------------- elementwise / reduction kernels ----------------

__global__ void cvt_kernel(const float* __restrict__ s, __nv_bfloat16* __restrict__ d, int n4){
    for (int i = blockIdx.x*blockDim.x + threadIdx.x; i < n4; i += gridDim.x*blockDim.x){
        float4 v = reinterpret_cast<const float4*>(s)[i];
        __nv_bfloat162* o = reinterpret_cast<__nv_bfloat162*>(d) + (long long)i*2;
        o[0] = __floats2bfloat162_rn(v.x, v.y);
        o[1] = __floats2bfloat162_rn(v.z, v.w);
    }
}

__global__ void __launch_bounds__(256) router_kernel(const float* __restrict__ x,
                                                     const float* __restrict__ wr){
    int row = blockIdx.x*8 + (threadIdx.x >> 5);
    int lane = threadIdx.x & 31;
    const float* xr = x + (long long)row * D_;
    float s = 0.f;
    #pragma unroll 8
    for (int i = lane; i < D_; i += 32) s += xr[i] * wr[i];
    #pragma unroll
    for (int o=16;o;o>>=1) s += __shfl_xor_sync(0xffffffffu, s, o);
    if (!lane) g_logits[row] = s;
}

__global__ void __launch_bounds__(1024) topk_kernel(){
    __shared__ float sv[S_];
    __shared__ int   scn[1024];
    __shared__ float selv[T_];
    __shared__ float red[1024];
    int b = blockIdx.x, tid = threadIdx.x;
    for (int i = tid; i < S_; i += 1024) sv[i] = g_logits[b*S_ + i];
    __syncthreads();
    int base_i = tid*4;
    float v[4]; int rank[4] = {0,0,0,0};
    #pragma unroll
    for (int e=0;e<4;e++) v[e] = sv[base_i+e];
    for (int j=0;j<S_;j++){
        float vj = sv[j];
        #pragma unroll
        for (int e=0;e<4;e++)
            rank[e] += (vj > v[e]) || (vj == v[e] && j < base_i+e);
    }
    int flag[4]; int cnt = 0;
    #pragma unroll
    for (int e=0;e<4;e++){ flag[e] = rank[e] < T_; cnt += flag[e]; }
    scn[tid] = cnt; __syncthreads();
    for (int off=1; off<1024; off<<=1){
        int t = 0;
        if (tid >= off) t = scn[tid-off];
        __syncthreads();
        scn[tid] += t;
        __syncthreads();
    }
    int pos = scn[tid] - cnt;
    #pragma unroll
    for (int e=0;e<4;e++){
        int i = base_i + e;
        int p = -1;
        if (flag[e]){ p = pos++; g_sel[b*T_+p] = i; selv[p] = v[e]; }
        g_pos[b*S_ + i] = p;
    }
    __syncthreads();
    float sval = selv[tid];
    red[tid] = sval; __syncthreads();
    for (int off=512; off; off>>=1){ if (tid < off) red[tid] = fmaxf(red[tid], red[tid+off]); __syncthreads(); }
    float mx = red[0]; __syncthreads();
    float ex = __expf(sval - mx);
    red[tid] = ex; __syncthreads();
    for (int off=512; off; off>>=1){ if (tid < off) red[tid] += red[tid+off]; __syncthreads(); }
    g_rw[b*T_ + tid] = ex / red[0];
}

__device__ __forceinline__ float block_sum_256(float v, float* sh){
    #pragma unroll
    for (int o=16;o;o>>=1) v += __shfl_xor_sync(0xffffffffu, v, o);
    if ((threadIdx.x & 31) == 0) sh[threadIdx.x >> 5] = v;
    __syncthreads();
    if (threadIdx.x == 0){ float t=0; for (int w=0;w<8;w++) t += sh[w]; sh[0] = t; }
    __syncthreads();
    float r = sh[0];
    __syncthreads();
    return r;
}

__global__ void __launch_bounds__(256) gather_rms_kernel(const float* __restrict__ x,
                                                         const float* __restrict__ g1){
    __shared__ float sh[8];
    int bt = blockIdx.x;
    int b = bt >> 10;
    int s = g_sel[bt];
    const float* xr = x + ((long long)b*S_ + s) * D_;
    float vals[8]; float ss = 0.f;
    #pragma unroll
    for (int e=0;e<8;e++){ float val = xr[threadIdx.x + e*256]; vals[e] = val; ss += val*val; }
    float tot = block_sum_256(ss, sh);
    float inv = rsqrtf(tot / D_ + 1e-6f);
    long long base = (long long)bt * D_;
    #pragma unroll
    for (int e=0;e<8;e++){
        int d = threadIdx.x + e*256;
        g_fx[base+d] = vals[e];
        g_h[base+d]  = __float2bfloat16(vals[e] * inv * g1[d]);
    }
}

__global__ void __launch_bounds__(128) rope_pack_kernel(const float* __restrict__ f){
    int idx = blockIdx.x;
    int t  = idx & (T_-1);
    int bh = idx >> 10;
    int h  = bh & (H_-1);
    int b  = bh >> 4;
    int d  = threadIdx.x;
    long long src = ((long long)(b*T_ + t)) * D_ + h*HD_;
    long long dst = ((long long)(b*H_ + h) * T_ + t) * HD_ + d;
    float qv = g_q[src+d], kv = g_k[src+d], vv = g_v[src+d];
    float qo, ko;
    if (d < 64){
        float c = f[(t*64 + d)*2], sn = f[(t*64 + d)*2 + 1];
        qo = qv*c - g_q[src+d+64]*sn;
        ko = kv*c - g_k[src+d+64]*sn;
    } else {
        int j = d - 64;
        float c = f[(t*64 + j)*2], sn = f[(t*64 + j)*2 + 1];
        qo = g_q[src+j]*sn + qv*c;
        ko = g_k[src+j]*sn + kv*c;
    }
    g_qb[dst] = __float2bfloat16(qo);
    g_kb[dst] = __float2bfloat16(ko);
    g_vb[dst] = __float2bfloat16(vv);
}

__global__ void __launch_bounds__(256) softmax_kernel(){
    __shared__ float shw[8];
    __shared__ float res;
    long long row = blockIdx.x;
    const float* sr = g_scores + row * T_;
    __nv_bfloat16* pr = g_probs + row * T_;
    float v[4]; float mx = -1e30f;
    #pragma unroll
    for (int e=0;e<4;e++){ v[e] = sr[threadIdx.x + e*256] * 0.08838834764831845f; mx = fmaxf(mx, v[e]); }
    #pragma unroll
    for (int o=16;o;o>>=1) mx = fmaxf(mx, __shfl_xor_sync(0xffffffffu, mx, o));
    if ((threadIdx.x & 31) == 0) shw[threadIdx.x >> 5] = mx;
    __syncthreads();
    if (threadIdx.x == 0){ float t = shw[0]; for (int w=1;w<8;w++) t = fmaxf(t, shw[w]); res = t; }
    __syncthreads();
    mx = res;
    __syncthreads();
    float ex[4]; float sum = 0.f;
    #pragma unroll
    for (int e=0;e<4;e++){ ex[e] = __expf(v[e] - mx); sum += ex[e]; }
    #pragma unroll
    for (int o=16;o;o>>=1) sum += __shfl_xor_sync(0xffffffffu, sum, o);
    if ((threadIdx.x & 31) == 0) shw[threadIdx.x >> 5] = sum;
    __syncthreads();
    if (threadIdx.x == 0){ float t=0; for (int w=0;w<8;w++) t += shw[w]; res = t; }
    __syncthreads();
    float rinv = __frcp_rn(res);
    #pragma unroll
    for (int e=0;e<4;e++) pr[threadIdx.x + e*256] = __float2bfloat16(ex[e] * rinv);
}

__global__ void __launch_bounds__(128) perm_o_kernel(){
    int idx = blockIdx.x;
    int t  = idx & (T_-1);
    int bh = idx >> 10;
    int h  = bh & (H_-1);
    int b  = bh >> 4;
    int d  = threadIdx.x;
    g_ob[((long long)(b*T_ + t)) * D_ + h*HD_ + d] =
        __float2bfloat16(g_o[((long long)(b*H_ + h) * T_ + t) * HD_ + d]);
}

__global__ void __launch_bounds__(256) resid_rms_kernel(const float* __restrict__ g2){
    __shared__ float sh[8];
    long long base = (long long)blockIdx.x * D_;
    float vals[8]; float ss = 0.f;
    #pragma unroll
    for (int e=0;e<8;e++){
        int d = threadIdx.x + e*256;
        float val = g_fx[base+d] + g_y[base+d];
        vals[e] = val; ss += val*val;
    }
    float tot = block_sum_256(ss, sh);
    float inv = rsqrtf(tot / D_ + 1e-6f);
    #pragma unroll
    for (int e=0;e<8;e++){
        int d = threadIdx.x + e*256;
        g_x1[base+d] = vals[e];
        g_h2[base+d] = __float2bfloat16(vals[e] * inv * g2[d]);
    }
}

__global__ void act_kernel(){
    const int n4 = M_*F_/4;
    for (int i = blockIdx.x*blockDim.x + threadIdx.x; i < n4; i += gridDim.x*blockDim.x){
        float4 u = reinterpret_cast<const float4*>(g_u)[i];
        float4 g = reinterpret_cast<const float4*>(g_g)[i];
        float a0 = __fdividef(u.x, 1.f + __expf(-u.x)) * g.x;
        float a1 = __fdividef(u.y, 1.f + __expf(-u.y)) * g.y;
        float a2 = __fdividef(u.z, 1.f + __expf(-u.z)) * g.z;
        float a3 = __fdividef(u.w, 1.f + __expf(-u.w)) * g.w;
        __nv_bfloat162* o = reinterpret_cast<__nv_bfloat162*>(g_act) + (long long)i*2;
        o[0] = __floats2bfloat162_rn(a0, a1);
        o[1] = __floats2bfloat162_rn(a2, a3);
    }
}

__global__ void __launch_bounds__(256) final_kernel(const float* __restrict__ x,
                                                    float* __restrict__ out){
    int bs = blockIdx.x;
    int b = bs >> 12;
    int pos = g_pos[bs];
    long long rb = (long long)bs * D_;
    if (pos < 0){
        #pragma unroll
        for (int e=0;e<2;e++){
            int i = threadIdx.x + e*256;
            reinterpret_cast<float4*>(out + rb)[i] =
                reinterpret_cast<const float4*>(x + rb)[i];
        }
    } else {
        float w = g_rw[b*T_ + pos];
        long long ob = ((long long)b*T_ + pos) * D_;
        #pragma unroll
        for (int e=0;e<8;e++){
            int d = threadIdx.x + e*256;
            out[rb+d] = x[rb+d] + w * (g_x1[ob+d] + g_y[ob+d]);
        }
    }
}

// ---------------- host orchestration ----------------
#define GETP(sym_) ([&]{ void* p_ = nullptr; cudaGetSymbolAddress(&p_, sym_); return p_; }())

extern "C" void kernel_launch(void* const* d_in, const int* in_sizes, int n_in,
                              void* d_out, int out_size)
{
    const float* x     = (const float*)d_in[0];
    const float* freqs = (const float*)d_in[2];
    const float* wr    = (const float*)d_in[3];
    const float* g1    = (const float*)d_in[4];
    const float* wq    = (const float*)d_in[5];
    const float* wk    = (const float*)d_in[6];
    const float* wv    = (const float*)d_in[7];
    const float* wo    = (const float*)d_in[8];
    const float* g2    = (const float*)d_in[9];
    const float* w1    = (const float*)d_in[10];
    const float* w3    = (const float*)d_in[11];
    const float* w2    = (const float*)d_in[12];
    float* out = (float*)d_out;

    static bool attr_set = false;
    if (!attr_set){
        cudaFuncSetAttribute(gemm2<0>, cudaFuncAttributeMaxDynamicSharedMemorySize, GEMM_SMEM);
        cudaFuncSetAttribute(gemm2<1>, cudaFuncAttributeMaxDynamicSharedMemorySize, GEMM_SMEM);
        attr_set = true;
    }

    __nv_bfloat16* p_wq = (__nv_bfloat16*)GETP(g_wq_b);
    __nv_bfloat16* p_wk = (__nv_bfloat16*)GETP(g_wk_b);
    __nv_bfloat16* p_wv = (__nv_bfloat16*)GETP(g_wv_b);
    __nv_bfloat16* p_wo = (__nv_bfloat16*)GETP(g_wo_b);
    __nv_bfloat16* p_w1 = (__nv_bfloat16*)GETP(g_w1_b);
    __nv_bfloat16* p_w3 = (__nv_bfloat16*)GETP(g_w3_b);
    __nv_bfloat16* p_w2 = (__nv_bfloat16*)GETP(g_w2_b);
    __nv_bfloat16* p_h  = (__nv_bfloat16*)GETP(g_h);
    __nv_bfloat16* p_qb = (__nv_bfloat16*)GETP(g_qb);
    __nv_bfloat16* p_kb = (__nv_bfloat16*)GETP(g_kb);
    __nv_bfloat16* p_vb = (__nv_bfloat16*)GETP(g_vb);
    __nv_bfloat16* p_pr = (__nv_bfloat16*)GETP(g_probs);
    __nv_bfloat16* p_ob = (__nv_bfloat16*)GETP(g_ob);
    __nv_bfloat16* p_h2 = (__nv_bfloat16*)GETP(g_h2);
    __nv_bfloat16* p_ac = (__nv_bfloat16*)GETP(g_act);
    float* p_q  = (float*)GETP(g_q);
    float* p_k  = (float*)GETP(g_k);
    float* p_v  = (float*)GETP(g_v);
    float* p_sc = (float*)GETP(g_scores);
    float* p_o  = (float*)GETP(g_o);
    float* p_u  = (float*)GETP(g_u);
    float* p_g  = (float*)GETP(g_g);
    float* p_y  = (float*)GETP(g_y);

    // 1) weight conversions fp32 -> bf16 (no transpose needed)
    cvt_kernel<<<2048,256>>>(wq, p_wq, D_*D_/4);
    cvt_kernel<<<2048,256>>>(wk, p_wk, D_*D_/4);
    cvt_kernel<<<2048,256>>>(wv, p_wv, D_*D_/4);
    cvt_kernel<<<2048,256>>>(wo, p_wo, D_*D_/4);
    cvt_kernel<<<4096,256>>>(w1, p_w1, D_*F_/4);
    cvt_kernel<<<4096,256>>>(w3, p_w3, D_*F_/4);
    cvt_kernel<<<4096,256>>>(w2, p_w2, F_*D_/4);

    // 2) router + exact top-k + softmax weights
    router_kernel<<<B_*S_/8, 256>>>(x, wr);
    topk_kernel<<<B_, 1024>>>();

    // 3) gather + rmsnorm1
    gather_rms_kernel<<<M_, 256>>>(x, g1);

    // 4) QKV GEMMs
    gemm2<0><<<dim3(D_/BN, M_/BM, 1), 256, GEMM_SMEM>>>(p_h, p_wq, p_q, D_, D_, D_, D_, 0,0,0);
    gemm2<0><<<dim3(D_/BN, M_/BM, 1), 256, GEMM_SMEM>>>(p_h, p_wk, p_k, D_, D_, D_, D_, 0,0,0);
    gemm2<0><<<dim3(D_/BN, M_/BM, 1), 256, GEMM_SMEM>>>(p_h, p_wv, p_v, D_, D_, D_, D_, 0,0,0);

    // 5) RoPE + pack to [b,h,t,hd] bf16
    rope_pack_kernel<<<B_*H_*T_, 128>>>(freqs);

    // 6) scores = Q K^T per (b,h)  (BT=1, K=HD=128)
    gemm2<1><<<dim3(T_/BN, T_/BM, B_*H_), 256, GEMM_SMEM>>>(p_qb, p_kb, p_sc,
        HD_, HD_, HD_, T_, (long long)T_*HD_, (long long)T_*HD_, (long long)T_*T_);

    // 7) softmax -> bf16 probs
    softmax_kernel<<<B_*H_*T_, 256>>>();

    // 8) O = P V per (b,h)
    gemm2<0><<<dim3(1, T_/BM, B_*H_), 256, GEMM_SMEM>>>(p_pr, p_vb, p_o,
        T_, T_, HD_, HD_, (long long)T_*T_, (long long)T_*HD_, (long long)T_*HD_);

    // 9) permute o -> [b,t,d] bf16, project with wo
    perm_o_kernel<<<B_*H_*T_, 128>>>();
    gemm2<0><<<dim3(D_/BN, M_/BM, 1), 256, GEMM_SMEM>>>(p_ob, p_wo, p_y, D_, D_, D_, D_, 0,0,0);

    // 10) residual + rmsnorm2
    resid_rms_kernel<<<M_, 256>>>(g2);

    // 11) FFN
    gemm2<0><<<dim3(F_/BN, M_/BM, 1), 256, GEMM_SMEM>>>(p_h2, p_w1, p_u, D_, D_, F_, F_, 0,0,0);
    gemm2<0><<<dim3(F_/BN, M_/BM, 1), 256, GEMM_SMEM>>>(p_h2, p_w3, p_g, D_, D_, F_, F_, 0,0,0);
    act_kernel<<<8192, 256>>>();
    gemm2<0><<<dim3(D_/BN, M_/BM, 1), 256, GEMM_SMEM>>>(p_ac, p_w2, p_y, F_, F_, D_, D_, 0,0,0);

    // 12) final scatter-add
    final_kernel<<<B_*S_, 256>>>(x, out);
}

// round 4
// speedup vs baseline: 1.7230x; 1.5046x over previous
#include <cuda_runtime.h>
#include <cuda_bf16.h>
#include <cstdint>

// Problem dims
#define B_  4
#define S_  4096
#define D_  2048
#define T_  1024
#define H_  16
#define HD_ 128
#define F_  8192
#define M_  (B_*T_)

// ---------------- device scratch ----------------
#define DEVBUF(type, name, count) __device__ __align__(256) type name[count]

DEVBUF(__nv_bfloat16, g_wq_b, D_*D_);
DEVBUF(__nv_bfloat16, g_wk_b, D_*D_);
DEVBUF(__nv_bfloat16, g_wv_b, D_*D_);
DEVBUF(__nv_bfloat16, g_wo_b, D_*D_);
DEVBUF(__nv_bfloat16, g_w1_b, D_*F_);
DEVBUF(__nv_bfloat16, g_w3_b, D_*F_);
DEVBUF(__nv_bfloat16, g_w2_b, F_*D_);

DEVBUF(float, g_logits, B_*S_);
DEVBUF(int,   g_sel,    B_*T_);
DEVBUF(int,   g_pos,    B_*S_);
DEVBUF(float, g_rw,     B_*T_);

DEVBUF(float,         g_fx,  M_*D_);
DEVBUF(__nv_bfloat16, g_h,   M_*D_);
DEVBUF(float,         g_q,   M_*D_);
DEVBUF(float,         g_k,   M_*D_);
DEVBUF(float,         g_v,   M_*D_);
DEVBUF(__nv_bfloat16, g_qb,  M_*D_);     // [b,h,t,hd]
DEVBUF(__nv_bfloat16, g_kb,  M_*D_);
DEVBUF(__nv_bfloat16, g_vb,  M_*D_);
DEVBUF(float,         g_scores, (long long)B_*H_*T_*T_);
DEVBUF(__nv_bfloat16, g_probs,  (long long)B_*H_*T_*T_);
DEVBUF(float,         g_o,   M_*D_);
DEVBUF(__nv_bfloat16, g_ob,  M_*D_);
DEVBUF(float,         g_x1,  M_*D_);
DEVBUF(__nv_bfloat16, g_h2,  M_*D_);
DEVBUF(float,         g_u,   M_*F_);
DEVBUF(float,         g_g,   M_*F_);
DEVBUF(__nv_bfloat16, g_act, M_*F_);
DEVBUF(float,         g_y,   M_*D_);

// ---------------- raw mma.sync GEMM ----------------
// C[M,N] fp32 = A[M,K](row) * B ; BT=0: B[K,N] row-major ; BT=1: B[N,K] row-major (C = A B^T)
// CTA 128x128, BK=64, 3-stage cp.async, 8 warps of 32x64, ldmatrix + mma.m16n8k16.

#define BM 128
#define BN 128
#define BK 64
#define STAGE_B 32768                 // 16KB A + 16KB B
#define GEMM_SMEM (3*STAGE_B)         // 98304

__device__ __forceinline__ uint32_t smem_u32(const void* p){
    uint32_t a;
    asm("{ .reg .u64 t; cvta.to.shared.u64 t, %1; cvt.u32.u64 %0, t; }" : "=r"(a) : "l"(p));
    return a;
}
__device__ __forceinline__ void cpasync16(uint32_t dst, const void* src){
    asm volatile("cp.async.cg.shared.global [%0], [%1], 16;" :: "r"(dst), "l"(src));
}
__device__ __forceinline__ void ldsm_x4(uint32_t* r, uint32_t addr){
    asm volatile("ldmatrix.sync.aligned.m8n8.x4.shared.b16 {%0,%1,%2,%3}, [%4];"
        : "=r"(r[0]), "=r"(r[1]), "=r"(r[2]), "=r"(r[3]) : "r"(addr));
}
__device__ __forceinline__ void ldsm_x4_t(uint32_t* r, uint32_t addr){
    asm volatile("ldmatrix.sync.aligned.m8n8.x4.trans.shared.b16 {%0,%1,%2,%3}, [%4];"
        : "=r"(r[0]), "=r"(r[1]), "=r"(r[2]), "=r"(r[3]) : "r"(addr));
}
__device__ __forceinline__ void mma16816(float* c, const uint32_t* a, uint32_t b0, uint32_t b1){
    asm volatile("mma.sync.aligned.m16n8k16.row.col.f32.bf16.bf16.f32 "
        "{%0,%1,%2,%3}, {%4,%5,%6,%7}, {%8,%9}, {%0,%1,%2,%3};"
        : "+f"(c[0]), "+f"(c[1]), "+f"(c[2]), "+f"(c[3])
        : "r"(a[0]), "r"(a[1]), "r"(a[2]), "r"(a[3]), "r"(b0), "r"(b1));
}

// A (and BT=1 B) tile: 128 rows x 64 bf16 (128B rows, XOR-8 swizzle on 16B chunks)
__device__ __forceinline__ void ldA_128x64(const __nv_bfloat16* g, int ld, uint32_t sbase, int tid){
    #pragma unroll
    for (int i = 0; i < 4; i++){
        int ch = tid + i*256;
        int r = ch >> 3, c = ch & 7;
        cpasync16(sbase + r*128 + (((c ^ (r & 7))) << 4),
                  (const char*)(g + (long long)r*ld) + c*16);
    }
}
// BT=0 B tile: 64 rows x 128 bf16 (256B rows; swizzle within each 128B half)
__device__ __forceinline__ void ldB_64x128(const __nv_bfloat16* g, int ld, uint32_t sbase, int tid){
    #pragma unroll
    for (int i = 0; i < 4; i++){
        int ch = tid + i*256;
        int r = ch >> 4, c = ch & 15;
        int half = c >> 3, c8 = c & 7;
        cpasync16(sbase + r*256 + half*128 + ((c8 ^ (r & 7)) << 4),
                  (const char*)(g + (long long)r*ld) + c*16);
    }
}

template<int BT>
__global__ void __launch_bounds__(256, 2) gemm3(
    const __nv_bfloat16* __restrict__ A, const __nv_bfloat16* __restrict__ Bm,
    float* __restrict__ C, int K, int lda, int ldb, int ldc,
    long long sA, long long sB, long long sC)
{
    extern __shared__ char smem[];
    uint32_t sb = smem_u32(smem);
    int tid = threadIdx.x, warp = tid >> 5, lane = tid & 31;
    int z = blockIdx.z;
    const __nv_bfloat16* Ab = A + (long long)z*sA + (long long)blockIdx.y*BM*lda;
    const __nv_bfloat16* Bb = Bm + (long long)z*sB;
    float* Cb = C + (long long)z*sC;
    const int bn = blockIdx.x*BN;

    int wm = (warp & 3) * 32;
    int wn = (warp >> 2) * 64;

    float acc[2][8][4];
    #pragma unroll
    for (int i=0;i<2;i++)
        #pragma unroll
        for (int j=0;j<8;j++)
            #pragma unroll
            for (int e=0;e<4;e++) acc[i][j][e] = 0.f;

    const int NS = K >> 6;

    auto load_stage = [&](int s){
        uint32_t base = sb + (s % 3)*STAGE_B;
        int k0 = s*BK;
        ldA_128x64(Ab + k0, lda, base, tid);
        if (BT == 0) ldB_64x128(Bb + (long long)k0*ldb + bn, ldb, base + 16384, tid);
        else         ldA_128x64(Bb + (long long)bn*ldb + k0, ldb, base + 16384, tid);
        asm volatile("cp.async.commit_group;" ::: "memory");
    };

    load_stage(0);
    if (NS > 1) load_stage(1);

    // per-lane invariant address components
    int a_row_lo = wm + ((lane >> 3) & 1)*8 + (lane & 7);      // + ii*16
    int a_kq     = (lane >> 4) * 8;                            // + kk
    int b1_row   = wn + (lane >> 4)*8 + (lane & 7);            // + jj*16 (BT=1)
    int b1_kq    = ((lane >> 3) & 1) * 8;
    int b0_krow  = ((lane >> 3) & 1)*8 + (lane & 7);           // + kk (BT=0)
    int b0_ncol  = wn + (lane >> 4)*8;                         // + jj*16

    for (int s = 0; s < NS; s++){
        if (s + 1 < NS) asm volatile("cp.async.wait_group 1;" ::: "memory");
        else            asm volatile("cp.async.wait_group 0;" ::: "memory");
        __syncthreads();

        if (s + 2 < NS) load_stage(s + 2);

        uint32_t Abase = sb + (s % 3)*STAGE_B;
        uint32_t Bbase = Abase + 16384;

        #pragma unroll
        for (int kk = 0; kk < BK; kk += 16){
            uint32_t af[2][4];
            #pragma unroll
            for (int ii = 0; ii < 2; ii++){
                int mrow = a_row_lo + ii*16;
                int kb = kk + a_kq;
                ldsm_x4(af[ii], Abase + mrow*128 + ((((kb >> 3) ^ (mrow & 7))) << 4));
            }
            uint32_t bf[4][4];
            #pragma unroll
            for (int jj = 0; jj < 4; jj++){
                if (BT == 1){
                    int nrow = b1_row + jj*16;
                    int kb = kk + b1_kq;
                    ldsm_x4(bf[jj], Bbase + nrow*128 + ((((kb >> 3) ^ (nrow & 7))) << 4));
                } else {
                    int krow = kk + b0_krow;
                    int ncol = b0_ncol + jj*16;
                    ldsm_x4_t(bf[jj], Bbase + krow*256 + ((ncol >> 6) & 1)*128
                                     + ((((ncol >> 3) & 7) ^ (krow & 7)) << 4));
                }
            }
            #pragma unroll
            for (int ii = 0; ii < 2; ii++)
                #pragma unroll
                for (int jj = 0; jj < 4; jj++){
                    mma16816(acc[ii][2*jj],   af[ii], bf[jj][0], bf[jj][1]);
                    mma16816(acc[ii][2*jj+1], af[ii], bf[jj][2], bf[jj][3]);
                }
        }
        __syncthreads();
    }

    // epilogue: direct float2 stores
    #pragma unroll
    for (int ii = 0; ii < 2; ii++){
        int r0 = blockIdx.y*BM + wm + ii*16 + (lane >> 2);
        #pragma unroll
        for (int j8 = 0; j8 < 8; j8++){
            int c0 = bn + wn + j8*8 + (lane & 3)*2;
            float* p0 = Cb + (long long)r0*ldc + c0;
            float* p1 = p0 + 8*ldc;
            *reinterpret_cast<float2*>(p0) = make_float2(acc[ii][j8][0], acc[ii][j8][1]);
            *reinterpret_cast<float2*>(p1) = make_float2(acc[ii][j8][2], acc[ii][j8][3]);
        }
    }
}

// ---------------- elementwise / reduction kernels ----------------

__global__ void cvt_kernel(const float* __restrict__ s, __nv_bfloat16* __restrict__ d, int n4){
    for (int i = blockIdx.x*blockDim.x + threadIdx.x; i < n4; i += gridDim.x*blockDim.x){
        float4 v = reinterpret_cast<const float4*>(s)[i];
        __nv_bfloat162* o = reinterpret_cast<__nv_bfloat162*>(d) + (long long)i*2;
        o[0] = __floats2bfloat162_rn(v.x, v.y);
        o[1] = __floats2bfloat162_rn(v.z, v.w);
    }
}

__global__ void __launch_bounds__(256) router_kernel(const float* __restrict__ x,
                                                     const float* __restrict__ wr){
    int row = blockIdx.x*8 + (threadIdx.x >> 5);
    int lane = threadIdx.x & 31;
    const float* xr = x + (long long)row * D_;
    float s = 0.f;
    #pragma unroll 8
    for (int i = lane; i < D_; i += 32) s += xr[i] * wr[i];
    #pragma unroll
    for (int o=16;o;o>>=1) s += __shfl_xor_sync(0xffffffffu, s, o);
    if (!lane) g_logits[row] = s;
}

__global__ void __launch_bounds__(1024) topk_kernel(){
    __shared__ float sv[S_];
    __shared__ int   scn[1024];
    __shared__ float selv[T_];
    __shared__ float red[1024];
    int b = blockIdx.x, tid = threadIdx.x;
    for (int i = tid; i < S_; i += 1024) sv[i] = g_logits[b*S_ + i];
    __syncthreads();
    int base_i = tid*4;
    float v[4]; int rank[4] = {0,0,0,0};
    #pragma unroll
    for (int e=0;e<4;e++) v[e] = sv[base_i+e];
    for (int j=0;j<S_;j++){
        float vj = sv[j];
        #pragma unroll
        for (int e=0;e<4;e++)
            rank[e] += (vj > v[e]) || (vj == v[e] && j < base_i+e);
    }
    int flag[4]; int cnt = 0;
    #pragma unroll
    for (int e=0;e<4;e++){ flag[e] = rank[e] < T_; cnt += flag[e]; }
    scn[tid] = cnt; __syncthreads();
    for (int off=1; off<1024; off<<=1){
        int t = 0;
        if (tid >= off) t = scn[tid-off];
        __syncthreads();
        scn[tid] += t;
        __syncthreads();
    }
    int pos = scn[tid] - cnt;
    #pragma unroll
    for (int e=0;e<4;e++){
        int i = base_i + e;
        int p = -1;
        if (flag[e]){ p = pos++; g_sel[b*T_+p] = i; selv[p] = v[e]; }
        g_pos[b*S_ + i] = p;
    }
    __syncthreads();
    float sval = selv[tid];
    red[tid] = sval; __syncthreads();
    for (int off=512; off; off>>=1){ if (tid < off) red[tid] = fmaxf(red[tid], red[tid+off]); __syncthreads(); }
    float mx = red[0]; __syncthreads();
    float ex = __expf(sval - mx);
    red[tid] = ex; __syncthreads();
    for (int off=512; off; off>>=1){ if (tid < off) red[tid] += red[tid+off]; __syncthreads(); }
    g_rw[b*T_ + tid] = ex / red[0];
}

__device__ __forceinline__ float block_sum_256(float v, float* sh){
    #pragma unroll
    for (int o=16;o;o>>=1) v += __shfl_xor_sync(0xffffffffu, v, o);
    if ((threadIdx.x & 31) == 0) sh[threadIdx.x >> 5] = v;
    __syncthreads();
    if (threadIdx.x == 0){ float t=0; for (int w=0;w<8;w++) t += sh[w]; sh[0] = t; }
    __syncthreads();
    float r = sh[0];
    __syncthreads();
    return r;
}

__global__ void __launch_bounds__(256) gather_rms_kernel(const float* __restrict__ x,
                                                         const float* __restrict__ g1){
    __shared__ float sh[8];
    int bt = blockIdx.x;
    int b = bt >> 10;
    int s = g_sel[bt];
    const float* xr = x + ((long long)b*S_ + s) * D_;
    float vals[8]; float ss = 0.f;
    #pragma unroll
    for (int e=0;e<8;e++){ float val = xr[threadIdx.x + e*256]; vals[e] = val; ss += val*val; }
    float tot = block_sum_256(ss, sh);
    float inv = rsqrtf(tot / D_ + 1e-6f);
    long long base = (long long)bt * D_;
    #pragma unroll
    for (int e=0;e<8;e++){
        int d = threadIdx.x + e*256;
        g_fx[base+d] = vals[e];
        g_h[base+d]  = __float2bfloat16(vals[e] * inv * g1[d]);
    }
}

__global__ void __launch_bounds__(128) rope_pack_kernel(const float* __restrict__ f){
    int idx = blockIdx.x;
    int t  = idx & (T_-1);
    int bh = idx >> 10;
    int h  = bh & (H_-1);
    int b  = bh >> 4;
    int d  = threadIdx.x;
    long long src = ((long long)(b*T_ + t)) * D_ + h*HD_;
    long long dst = ((long long)(b*H_ + h) * T_ + t) * HD_ + d;
    float qv = g_q[src+d], kv = g_k[src+d], vv = g_v[src+d];
    float qo, ko;
    if (d < 64){
        float c = f[(t*64 + d)*2], sn = f[(t*64 + d)*2 + 1];
        qo = qv*c - g_q[src+d+64]*sn;
        ko = kv*c - g_k[src+d+64]*sn;
    } else {
        int j = d - 64;
        float c = f[(t*64 + j)*2], sn = f[(t*64 + j)*2 + 1];
        qo = g_q[src+j]*sn + qv*c;
        ko = g_k[src+j]*sn + kv*c;
    }
    g_qb[dst] = __float2bfloat16(qo);
    g_kb[dst] = __float2bfloat16(ko);
    g_vb[dst] = __float2bfloat16(vv);
}

__global__ void __launch_bounds__(256) softmax_kernel(){
    __shared__ float shw[8];
    __shared__ float res;
    long long row = blockIdx.x;
    const float* sr = g_scores + row * T_;
    __nv_bfloat16* pr = g_probs + row * T_;
    float v[4]; float mx = -1e30f;
    #pragma unroll
    for (int e=0;e<4;e++){ v[e] = sr[threadIdx.x + e*256] * 0.08838834764831845f; mx = fmaxf(mx, v[e]); }
    #pragma unroll
    for (int o=16;o;o>>=1) mx = fmaxf(mx, __shfl_xor_sync(0xffffffffu, mx, o));
    if ((threadIdx.x & 31) == 0) shw[threadIdx.x >> 5] = mx;
    __syncthreads();
    if (threadIdx.x == 0){ float t = shw[0]; for (int w=1;w<8;w++) t = fmaxf(t, shw[w]); res = t; }
    __syncthreads();
    mx = res;
    __syncthreads();
    float ex[4]; float sum = 0.f;
    #pragma unroll
    for (int e=0;e<4;e++){ ex[e] = __expf(v[e] - mx); sum += ex[e]; }
    #pragma unroll
    for (int o=16;o;o>>=1) sum += __shfl_xor_sync(0xffffffffu, sum, o);
    if ((threadIdx.x & 31) == 0) shw[threadIdx.x >> 5] = sum;
    __syncthreads();
    if (threadIdx.x == 0){ float t=0; for (int w=0;w<8;w++) t += shw[w]; res = t; }
    __syncthreads();
    float rinv = __frcp_rn(res);
    #pragma unroll
    for (int e=0;e<4;e++) pr[threadIdx.x + e*256] = __float2bfloat16(ex[e] * rinv);
}

__global__ void __launch_bounds__(128) perm_o_kernel(){
    int idx = blockIdx.x;
    int t  = idx & (T_-1);
    int bh = idx >> 10;
    int h  = bh & (H_-1);
    int b  = bh >> 4;
    int d  = threadIdx.x;
    g_ob[((long long)(b*T_ + t)) * D_ + h*HD_ + d] =
        __float2bfloat16(g_o[((long long)(b*H_ + h) * T_ + t) * HD_ + d]);
}

__global__ void __launch_bounds__(256) resid_rms_kernel(const float* __restrict__ g2){
    __shared__ float sh[8];
    long long base = (long long)blockIdx.x * D_;
    float vals[8]; float ss = 0.f;
    #pragma unroll
    for (int e=0;e<8;e++){
        int d = threadIdx.x + e*256;
        float val = g_fx[base+d] + g_y[base+d];
        vals[e] = val; ss += val*val;
    }
    float tot = block_sum_256(ss, sh);
    float inv = rsqrtf(tot / D_ + 1e-6f);
    #pragma unroll
    for (int e=0;e<8;e++){
        int d = threadIdx.x + e*256;
        g_x1[base+d] = vals[e];
        g_h2[base+d] = __float2bfloat16(vals[e] * inv * g2[d]);
    }
}

__global__ void act_kernel(){
    const int n4 = M_*F_/4;
    for (int i = blockIdx.x*blockDim.x + threadIdx.x; i < n4; i += gridDim.x*blockDim.x){
        float4 u = reinterpret_cast<const float4*>(g_u)[i];
        float4 g = reinterpret_cast<const float4*>(g_g)[i];
        float a0 = __fdividef(u.x, 1.f + __expf(-u.x)) * g.x;
        float a1 = __fdividef(u.y, 1.f + __expf(-u.y)) * g.y;
        float a2 = __fdividef(u.z, 1.f + __expf(-u.z)) * g.z;
        float a3 = __fdividef(u.w, 1.f + __expf(-u.w)) * g.w;
        __nv_bfloat162* o = reinterpret_cast<__nv_bfloat162*>(g_act) + (long long)i*2;
        o[0] = __floats2bfloat162_rn(a0, a1);
        o[1] = __floats2bfloat162_rn(a2, a3);
    }
}

__global__ void __launch_bounds__(256) final_kernel(const float* __restrict__ x,
                                                    float* __restrict__ out){
    int bs = blockIdx.x;
    int b = bs >> 12;
    int pos = g_pos[bs];
    long long rb = (long long)bs * D_;
    if (pos < 0){
        #pragma unroll
        for (int e=0;e<2;e++){
            int i = threadIdx.x + e*256;
            reinterpret_cast<float4*>(out + rb)[i] =
                reinterpret_cast<const float4*>(x + rb)[i];
        }
    } else {
        float w = g_rw[b*T_ + pos];
        long long ob = ((long long)b*T_ + pos) * D_;
        #pragma unroll
        for (int e=0;e<8;e++){
            int d = threadIdx.x + e*256;
            out[rb+d] = x[rb+d] + w * (g_x1[ob+d] + g_y[ob+d]);
        }
    }
}

// ---------------- host orchestration ----------------
#define GETP(sym_) ([&]{ void* p_ = nullptr; cudaGetSymbolAddress(&p_, sym_); return p_; }())

extern "C" void kernel_launch(void* const* d_in, const int* in_sizes, int n_in,
                              void* d_out, int out_size)
{
    const float* x     = (const float*)d_in[0];
    const float* freqs = (const float*)d_in[2];
    const float* wr    = (const float*)d_in[3];
    const float* g1    = (const float*)d_in[4];
    const float* wq    = (const float*)d_in[5];
    const float* wk    = (const float*)d_in[6];
    const float* wv    = (const float*)d_in[7];
    const float* wo    = (const float*)d_in[8];
    const float* g2    = (const float*)d_in[9];
    const float* w1    = (const float*)d_in[10];
    const float* w3    = (const float*)d_in[11];
    const float* w2    = (const float*)d_in[12];
    float* out = (float*)d_out;

    static bool attr_set = false;
    if (!attr_set){
        cudaFuncSetAttribute(gemm3<0>, cudaFuncAttributeMaxDynamicSharedMemorySize, GEMM_SMEM);
        cudaFuncSetAttribute(gemm3<1>, cudaFuncAttributeMaxDynamicSharedMemorySize, GEMM_SMEM);
        attr_set = true;
    }

    __nv_bfloat16* p_wq = (__nv_bfloat16*)GETP(g_wq_b);
    __nv_bfloat16* p_wk = (__nv_bfloat16*)GETP(g_wk_b);
    __nv_bfloat16* p_wv = (__nv_bfloat16*)GETP(g_wv_b);
    __nv_bfloat16* p_wo = (__nv_bfloat16*)GETP(g_wo_b);
    __nv_bfloat16* p_w1 = (__nv_bfloat16*)GETP(g_w1_b);
    __nv_bfloat16* p_w3 = (__nv_bfloat16*)GETP(g_w3_b);
    __nv_bfloat16* p_w2 = (__nv_bfloat16*)GETP(g_w2_b);
    __nv_bfloat16* p_h  = (__nv_bfloat16*)GETP(g_h);
    __nv_bfloat16* p_qb = (__nv_bfloat16*)GETP(g_qb);
    __nv_bfloat16* p_kb = (__nv_bfloat16*)GETP(g_kb);
    __nv_bfloat16* p_vb = (__nv_bfloat16*)GETP(g_vb);
    __nv_bfloat16* p_pr = (__nv_bfloat16*)GETP(g_probs);
    __nv_bfloat16* p_ob = (__nv_bfloat16*)GETP(g_ob);
    __nv_bfloat16* p_h2 = (__nv_bfloat16*)GETP(g_h2);
    __nv_bfloat16* p_ac = (__nv_bfloat16*)GETP(g_act);
    float* p_q  = (float*)GETP(g_q);
    float* p_k  = (float*)GETP(g_k);
    float* p_v  = (float*)GETP(g_v);
    float* p_sc = (float*)GETP(g_scores);
    float* p_o  = (float*)GETP(g_o);
    float* p_u  = (float*)GETP(g_u);
    float* p_g  = (float*)GETP(g_g);
    float* p_y  = (float*)GETP(g_y);

    // 1) weight conversions fp32 -> bf16
    cvt_kernel<<<2048,256>>>(wq, p_wq, D_*D_/4);
    cvt_kernel<<<2048,256>>>(wk, p_wk, D_*D_/4);
    cvt_kernel<<<2048,256>>>(wv, p_wv, D_*D_/4);
    cvt_kernel<<<2048,256>>>(wo, p_wo, D_*D_/4);
    cvt_kernel<<<4096,256>>>(w1, p_w1, D_*F_/4);
    cvt_kernel<<<4096,256>>>(w3, p_w3, D_*F_/4);
    cvt_kernel<<<4096,256>>>(w2, p_w2, F_*D_/4);

    // 2) router + exact top-k + softmax weights
    router_kernel<<<B_*S_/8, 256>>>(x, wr);
    topk_kernel<<<B_, 1024>>>();

    // 3) gather + rmsnorm1
    gather_rms_kernel<<<M_, 256>>>(x, g1);

    // 4) QKV GEMMs
    gemm3<0><<<dim3(D_/BN, M_/BM, 1), 256, GEMM_SMEM>>>(p_h, p_wq, p_q, D_, D_, D_, D_, 0,0,0);
    gemm3<0><<<dim3(D_/BN, M_/BM, 1), 256, GEMM_SMEM>>>(p_h, p_wk, p_k, D_, D_, D_, D_, 0,0,0);
    gemm3<0><<<dim3(D_/BN, M_/BM, 1), 256, GEMM_SMEM>>>(p_h, p_wv, p_v, D_, D_, D_, D_, 0,0,0);

    // 5) RoPE + pack to [b,h,t,hd] bf16
    rope_pack_kernel<<<B_*H_*T_, 128>>>(freqs);

    // 6) scores = Q K^T per (b,h)  (BT=1, K=HD=128)
    gemm3<1><<<dim3(T_/BN, T_/BM, B_*H_), 256, GEMM_SMEM>>>(p_qb, p_kb, p_sc,
        HD_, HD_, HD_, T_, (long long)T_*HD_, (long long)T_*HD_, (long long)T_*T_);

    // 7) softmax -> bf16 probs
    softmax_kernel<<<B_*H_*T_, 256>>>();

    // 8) O = P V per (b,h)
    gemm3<0><<<dim3(1, T_/BM, B_*H_), 256, GEMM_SMEM>>>(p_pr, p_vb, p_o,
        T_, T_, HD_, HD_, (long long)T_*T_, (long long)T_*HD_, (long long)T_*HD_);

    // 9) permute o -> [b,t,d] bf16, project with wo
    perm_o_kernel<<<B_*H_*T_, 128>>>();
    gemm3<0><<<dim3(D_/BN, M_/BM, 1), 256, GEMM_SMEM>>>(p_ob, p_wo, p_y, D_, D_, D_, D_, 0,0,0);

    // 10) residual + rmsnorm2
    resid_rms_kernel<<<M_, 256>>>(g2);

    // 11) FFN
    gemm3<0><<<dim3(F_/BN, M_/BM, 1), 256, GEMM_SMEM>>>(p_h2, p_w1, p_u, D_, D_, F_, F_, 0,0,0);
    gemm3<0><<<dim3(F_/BN, M_/BM, 1), 256, GEMM_SMEM>>>(p_h2, p_w3, p_g, D_, D_, F_, F_, 0,0,0);
    act_kernel<<<8192, 256>>>();
    gemm3<0><<<dim3(D_/BN, M_/BM, 1), 256, GEMM_SMEM>>>(p_ac, p_w2, p_y, F_, F_, D_, D_, 0,0,0);

    // 12) final scatter-add
    final_kernel<<<B_*S_, 256>>>(x, out);
}

// round 5
// speedup vs baseline: 1.8487x; 1.0730x over previous
#include <cuda_runtime.h>
#include <cuda_bf16.h>
#include <cstdint>

// Problem dims
#define B_  4
#define S_  4096
#define D_  2048
#define T_  1024
#define H_  16
#define HD_ 128
#define F_  8192
#define M_  (B_*T_)

// ---------------- device scratch ----------------
#define DEVBUF(type, name, count) __device__ __align__(256) type name[count]

DEVBUF(__nv_bfloat16, g_wq_b, D_*D_);
DEVBUF(__nv_bfloat16, g_wk_b, D_*D_);
DEVBUF(__nv_bfloat16, g_wv_b, D_*D_);
DEVBUF(__nv_bfloat16, g_wo_b, D_*D_);
DEVBUF(__nv_bfloat16, g_w1_b, D_*F_);
DEVBUF(__nv_bfloat16, g_w3_b, D_*F_);
DEVBUF(__nv_bfloat16, g_w2_b, F_*D_);

DEVBUF(float, g_logits, B_*S_);
DEVBUF(int,   g_sel,    B_*T_);
DEVBUF(int,   g_pos,    B_*S_);
DEVBUF(float, g_rw,     B_*T_);

DEVBUF(float,         g_fx,  M_*D_);
DEVBUF(__nv_bfloat16, g_h,   M_*D_);
DEVBUF(float,         g_q,   M_*D_);
DEVBUF(float,         g_k,   M_*D_);
DEVBUF(float,         g_v,   M_*D_);
DEVBUF(__nv_bfloat16, g_qb,  M_*D_);     // [b,h,t,hd]
DEVBUF(__nv_bfloat16, g_kb,  M_*D_);
DEVBUF(__nv_bfloat16, g_vb,  M_*D_);
DEVBUF(__nv_bfloat16, g_ob,  M_*D_);     // attn out [b,t,d] bf16
DEVBUF(float,         g_x1,  M_*D_);
DEVBUF(__nv_bfloat16, g_h2,  M_*D_);
DEVBUF(float,         g_u,   M_*F_);
DEVBUF(__nv_bfloat16, g_act, M_*F_);
DEVBUF(float,         g_y,   M_*D_);

// ---------------- PTX helpers ----------------
__device__ __forceinline__ uint32_t smem_u32(const void* p){
    uint32_t a;
    asm("{ .reg .u64 t; cvta.to.shared.u64 t, %1; cvt.u32.u64 %0, t; }" : "=r"(a) : "l"(p));
    return a;
}
__device__ __forceinline__ void cpasync16(uint32_t dst, const void* src){
    asm volatile("cp.async.cg.shared.global [%0], [%1], 16;" :: "r"(dst), "l"(src));
}
__device__ __forceinline__ void ldsm_x4(uint32_t* r, uint32_t addr){
    asm volatile("ldmatrix.sync.aligned.m8n8.x4.shared.b16 {%0,%1,%2,%3}, [%4];"
        : "=r"(r[0]), "=r"(r[1]), "=r"(r[2]), "=r"(r[3]) : "r"(addr));
}
__device__ __forceinline__ void ldsm_x4_t(uint32_t* r, uint32_t addr){
    asm volatile("ldmatrix.sync.aligned.m8n8.x4.trans.shared.b16 {%0,%1,%2,%3}, [%4];"
        : "=r"(r[0]), "=r"(r[1]), "=r"(r[2]), "=r"(r[3]) : "r"(addr));
}
__device__ __forceinline__ void mma16816(float* c, const uint32_t* a, uint32_t b0, uint32_t b1){
    asm volatile("mma.sync.aligned.m16n8k16.row.col.f32.bf16.bf16.f32 "
        "{%0,%1,%2,%3}, {%4,%5,%6,%7}, {%8,%9}, {%0,%1,%2,%3};"
        : "+f"(c[0]), "+f"(c[1]), "+f"(c[2]), "+f"(c[3])
        : "r"(a[0]), "r"(a[1]), "r"(a[2]), "r"(a[3]), "r"(b0), "r"(b1));
}
__device__ __forceinline__ uint32_t pack_bf16x2(float lo, float hi){
    __nv_bfloat162 v = __floats2bfloat162_rn(lo, hi);
    return *reinterpret_cast<uint32_t*>(&v);
}

// ---------------- raw mma.sync GEMM ----------------
// C[M,N] fp32 = A[M,K](row) * B ; BT=0: B[K,N] row-major ; BT=1: B[N,K] row-major
// EPI=0: fp32 store to C. EPI=1: silu(U[r,c]) * acc -> bf16 store to Obf.

#define BM 128
#define BN 128
#define BK 64
#define STAGE_B 32768
#define GEMM_SMEM (3*STAGE_B)

__device__ __forceinline__ void ldA_128x64(const __nv_bfloat16* g, int ld, uint32_t sbase, int tid){
    #pragma unroll
    for (int i = 0; i < 4; i++){
        int ch = tid + i*256;
        int r = ch >> 3, c = ch & 7;
        cpasync16(sbase + r*128 + (((c ^ (r & 7))) << 4),
                  (const char*)(g + (long long)r*ld) + c*16);
    }
}
__device__ __forceinline__ void ldB_64x128(const __nv_bfloat16* g, int ld, uint32_t sbase, int tid){
    #pragma unroll
    for (int i = 0; i < 4; i++){
        int ch = tid + i*256;
        int r = ch >> 4, c = ch & 15;
        int half = c >> 3, c8 = c & 7;
        cpasync16(sbase + r*256 + half*128 + ((c8 ^ (r & 7)) << 4),
                  (const char*)(g + (long long)r*ld) + c*16);
    }
}

template<int BT, int EPI>
__global__ void __launch_bounds__(256, 2) gemm3(
    const __nv_bfloat16* __restrict__ A, const __nv_bfloat16* __restrict__ Bm,
    float* __restrict__ C, int K, int lda, int ldb, int ldc,
    long long sA, long long sB, long long sC,
    const float* __restrict__ U, __nv_bfloat16* __restrict__ Obf)
{
    extern __shared__ char smem[];
    uint32_t sb = smem_u32(smem);
    int tid = threadIdx.x, warp = tid >> 5, lane = tid & 31;
    int z = blockIdx.z;
    const __nv_bfloat16* Ab = A + (long long)z*sA + (long long)blockIdx.y*BM*lda;
    const __nv_bfloat16* Bb = Bm + (long long)z*sB;
    float* Cb = C + (long long)z*sC;
    const int bn = blockIdx.x*BN;

    int wm = (warp & 3) * 32;
    int wn = (warp >> 2) * 64;

    float acc[2][8][4];
    #pragma unroll
    for (int i=0;i<2;i++)
        #pragma unroll
        for (int j=0;j<8;j++)
            #pragma unroll
            for (int e=0;e<4;e++) acc[i][j][e] = 0.f;

    const int NS = K >> 6;

    auto load_stage = [&](int s){
        uint32_t base = sb + (s % 3)*STAGE_B;
        int k0 = s*BK;
        ldA_128x64(Ab + k0, lda, base, tid);
        if (BT == 0) ldB_64x128(Bb + (long long)k0*ldb + bn, ldb, base + 16384, tid);
        else         ldA_128x64(Bb + (long long)bn*ldb + k0, ldb, base + 16384, tid);
        asm volatile("cp.async.commit_group;" ::: "memory");
    };

    load_stage(0);
    if (NS > 1) load_stage(1);

    int a_row_lo = wm + ((lane >> 3) & 1)*8 + (lane & 7);
    int a_kq     = (lane >> 4) * 8;
    int b1_row   = wn + (lane >> 4)*8 + (lane & 7);
    int b1_kq    = ((lane >> 3) & 1) * 8;
    int b0_krow  = ((lane >> 3) & 1)*8 + (lane & 7);
    int b0_ncol  = wn + (lane >> 4)*8;

    for (int s = 0; s < NS; s++){
        if (s + 1 < NS) asm volatile("cp.async.wait_group 1;" ::: "memory");
        else            asm volatile("cp.async.wait_group 0;" ::: "memory");
        __syncthreads();

        if (s + 2 < NS) load_stage(s + 2);

        uint32_t Abase = sb + (s % 3)*STAGE_B;
        uint32_t Bbase = Abase + 16384;

        #pragma unroll
        for (int kk = 0; kk < BK; kk += 16){
            uint32_t af[2][4];
            #pragma unroll
            for (int ii = 0; ii < 2; ii++){
                int mrow = a_row_lo + ii*16;
                int kb = kk + a_kq;
                ldsm_x4(af[ii], Abase + mrow*128 + ((((kb >> 3) ^ (mrow & 7))) << 4));
            }
            uint32_t bf[4][4];
            #pragma unroll
            for (int jj = 0; jj < 4; jj++){
                if (BT == 1){
                    int nrow = b1_row + jj*16;
                    int kb = kk + b1_kq;
                    ldsm_x4(bf[jj], Bbase + nrow*128 + ((((kb >> 3) ^ (nrow & 7))) << 4));
                } else {
                    int krow = kk + b0_krow;
                    int ncol = b0_ncol + jj*16;
                    ldsm_x4_t(bf[jj], Bbase + krow*256 + ((ncol >> 6) & 1)*128
                                     + ((((ncol >> 3) & 7) ^ (krow & 7)) << 4));
                }
            }
            #pragma unroll
            for (int ii = 0; ii < 2; ii++)
                #pragma unroll
                for (int jj = 0; jj < 4; jj++){
                    mma16816(acc[ii][2*jj],   af[ii], bf[jj][0], bf[jj][1]);
                    mma16816(acc[ii][2*jj+1], af[ii], bf[jj][2], bf[jj][3]);
                }
        }
        __syncthreads();
    }

    #pragma unroll
    for (int ii = 0; ii < 2; ii++){
        int r0 = blockIdx.y*BM + wm + ii*16 + (lane >> 2);
        #pragma unroll
        for (int j8 = 0; j8 < 8; j8++){
            int c0 = bn + wn + j8*8 + (lane & 3)*2;
            if (EPI == 0){
                float* p0 = Cb + (long long)r0*ldc + c0;
                float* p1 = p0 + 8*ldc;
                *reinterpret_cast<float2*>(p0) = make_float2(acc[ii][j8][0], acc[ii][j8][1]);
                *reinterpret_cast<float2*>(p1) = make_float2(acc[ii][j8][2], acc[ii][j8][3]);
            } else {
                long long i0 = (long long)r0*ldc + c0;
                long long i1 = i0 + 8*(long long)ldc;
                float2 u0 = *reinterpret_cast<const float2*>(U + i0);
                float2 u1 = *reinterpret_cast<const float2*>(U + i1);
                float s0 = __fdividef(u0.x, 1.f + __expf(-u0.x)) * acc[ii][j8][0];
                float s1 = __fdividef(u0.y, 1.f + __expf(-u0.y)) * acc[ii][j8][1];
                float s2 = __fdividef(u1.x, 1.f + __expf(-u1.x)) * acc[ii][j8][2];
                float s3 = __fdividef(u1.y, 1.f + __expf(-u1.y)) * acc[ii][j8][3];
                *reinterpret_cast<uint32_t*>(Obf + i0) = pack_bf16x2(s0, s1);
                *reinterpret_cast<uint32_t*>(Obf + i1) = pack_bf16x2(s2, s3);
            }
        }
    }
}

// ---------------- fused flash attention ----------------
// grid (T_/128, B_*H_), 256 threads. Q,K,V in [b,h,t,hd] bf16.
// Per warp: 16 q-rows; online softmax over 16 k-tiles of 64; O -> g_ob [b,t,d] bf16.

#define FA_STAGE 32768
#define FA_SMEM (32768 + 3*FA_STAGE)   // Q + 3 stages of (K|V)

__global__ void __launch_bounds__(256, 1) flash_kernel(
    const __nv_bfloat16* __restrict__ Q, const __nv_bfloat16* __restrict__ K,
    const __nv_bfloat16* __restrict__ V, __nv_bfloat16* __restrict__ Ob)
{
    extern __shared__ char smem[];
    uint32_t sq = smem_u32(smem);
    int tid = threadIdx.x, warp = tid >> 5, lane = tid & 31;
    int qt = blockIdx.x;
    int bh = blockIdx.y;
    int h = bh & (H_-1), b = bh >> 4;
    const __nv_bfloat16* Qb = Q + ((long long)bh*T_ + qt*128)*HD_;
    const __nv_bfloat16* Kb = K + (long long)bh*T_*HD_;
    const __nv_bfloat16* Vb = V + (long long)bh*T_*HD_;

    // load Q tile 128x128 (256B rows, swizzle per 128B half)
    #pragma unroll
    for (int i = 0; i < 8; i++){
        int ch = tid + i*256;
        int r = ch >> 4, c = ch & 15;
        cpasync16(sq + r*256 + (c >> 3)*128 + (((c & 7) ^ (r & 7)) << 4),
                  (const char*)(Qb + (long long)r*HD_) + c*16);
    }
    auto load_kv = [&](int s){
        uint32_t base = sq + 32768 + (s % 3)*FA_STAGE;
        const __nv_bfloat16* Kt = Kb + (long long)s*64*HD_;
        const __nv_bfloat16* Vt = Vb + (long long)s*64*HD_;
        #pragma unroll
        for (int i = 0; i < 4; i++){
            int ch = tid + i*256;
            int r = ch >> 4, c = ch & 15;
            uint32_t off = r*256 + (c >> 3)*128 + (((c & 7) ^ (r & 7)) << 4);
            cpasync16(base + off,         (const char*)(Kt + (long long)r*HD_) + c*16);
            cpasync16(base + 16384 + off, (const char*)(Vt + (long long)r*HD_) + c*16);
        }
        asm volatile("cp.async.commit_group;" ::: "memory");
    };
    load_kv(0);     // group includes Q
    load_kv(1);

    const int qr0 = warp*16;
    float o[16][4];
    #pragma unroll
    for (int j=0;j<16;j++)
        #pragma unroll
        for (int e=0;e<4;e++) o[j][e] = 0.f;
    float m0 = -1e30f, m1 = -1e30f, l0 = 0.f, l1 = 0.f;
    const float sc = 0.08838834764831845f;

    int a_row  = qr0 + ((lane >> 3) & 1)*8 + (lane & 7);
    int a_kq   = (lane >> 4) * 8;
    int b_row  = (lane >> 4)*8 + (lane & 7);
    int b_kq   = ((lane >> 3) & 1) * 8;
    int v_krow = ((lane >> 3) & 1)*8 + (lane & 7);
    int v_ncol = (lane >> 4) * 8;

    for (int s = 0; s < 16; s++){
        if (s + 1 < 16) asm volatile("cp.async.wait_group 1;" ::: "memory");
        else            asm volatile("cp.async.wait_group 0;" ::: "memory");
        __syncthreads();
        if (s + 2 < 16) load_kv(s + 2);

        uint32_t Kbase = sq + 32768 + (s % 3)*FA_STAGE;
        uint32_t Vbase = Kbase + 16384;

        float sv[8][4];
        #pragma unroll
        for (int j=0;j<8;j++)
            #pragma unroll
            for (int e=0;e<4;e++) sv[j][e] = 0.f;

        #pragma unroll
        for (int kk = 0; kk < 8; kk++){
            uint32_t af[4];
            int cA = (kk*16 + a_kq) >> 3;
            ldsm_x4(af, sq + a_row*256 + (cA >> 3)*128 + (((cA & 7) ^ (a_row & 7)) << 4));
            #pragma unroll
            for (int jj = 0; jj < 4; jj++){
                uint32_t bfm[4];
                int nrow = jj*16 + b_row;
                int cB = (kk*16 + b_kq) >> 3;
                ldsm_x4(bfm, Kbase + nrow*256 + (cB >> 3)*128 + (((cB & 7) ^ (nrow & 7)) << 4));
                mma16816(sv[2*jj],   af, bfm[0], bfm[1]);
                mma16816(sv[2*jj+1], af, bfm[2], bfm[3]);
            }
        }

        // online softmax (rows r0 = lane>>2 and r0+8)
        float rm0 = -1e30f, rm1 = -1e30f;
        #pragma unroll
        for (int j=0;j<8;j++){
            sv[j][0] *= sc; sv[j][1] *= sc; sv[j][2] *= sc; sv[j][3] *= sc;
            rm0 = fmaxf(rm0, fmaxf(sv[j][0], sv[j][1]));
            rm1 = fmaxf(rm1, fmaxf(sv[j][2], sv[j][3]));
        }
        rm0 = fmaxf(rm0, __shfl_xor_sync(0xffffffffu, rm0, 1));
        rm0 = fmaxf(rm0, __shfl_xor_sync(0xffffffffu, rm0, 2));
        rm1 = fmaxf(rm1, __shfl_xor_sync(0xffffffffu, rm1, 1));
        rm1 = fmaxf(rm1, __shfl_xor_sync(0xffffffffu, rm1, 2));
        float mn0 = fmaxf(m0, rm0), mn1 = fmaxf(m1, rm1);
        float rs0 = 0.f, rs1 = 0.f;
        #pragma unroll
        for (int j=0;j<8;j++){
            sv[j][0] = __expf(sv[j][0] - mn0);
            sv[j][1] = __expf(sv[j][1] - mn0);
            sv[j][2] = __expf(sv[j][2] - mn1);
            sv[j][3] = __expf(sv[j][3] - mn1);
            rs0 += sv[j][0] + sv[j][1];
            rs1 += sv[j][2] + sv[j][3];
        }
        rs0 += __shfl_xor_sync(0xffffffffu, rs0, 1);
        rs0 += __shfl_xor_sync(0xffffffffu, rs0, 2);
        rs1 += __shfl_xor_sync(0xffffffffu, rs1, 1);
        rs1 += __shfl_xor_sync(0xffffffffu, rs1, 2);
        float c0 = __expf(m0 - mn0), c1 = __expf(m1 - mn1);
        l0 = l0*c0 + rs0;  l1 = l1*c1 + rs1;
        m0 = mn0;  m1 = mn1;
        #pragma unroll
        for (int j=0;j<16;j++){
            o[j][0] *= c0; o[j][1] *= c0; o[j][2] *= c1; o[j][3] *= c1;
        }

        // O += P * V
        #pragma unroll
        for (int k2 = 0; k2 < 4; k2++){
            uint32_t pa[4];
            pa[0] = pack_bf16x2(sv[2*k2][0],   sv[2*k2][1]);
            pa[1] = pack_bf16x2(sv[2*k2][2],   sv[2*k2][3]);
            pa[2] = pack_bf16x2(sv[2*k2+1][0], sv[2*k2+1][1]);
            pa[3] = pack_bf16x2(sv[2*k2+1][2], sv[2*k2+1][3]);
            int krow = k2*16 + v_krow;
            #pragma unroll
            for (int jj = 0; jj < 8; jj++){
                uint32_t bv[4];
                int ncol = jj*16 + v_ncol;
                ldsm_x4_t(bv, Vbase + krow*256 + ((ncol >> 6) & 1)*128
                              + ((((ncol >> 3) & 7) ^ (krow & 7)) << 4));
                mma16816(o[2*jj],   pa, bv[0], bv[1]);
                mma16816(o[2*jj+1], pa, bv[2], bv[3]);
            }
        }
        __syncthreads();
    }

    float il0 = __frcp_rn(l0), il1 = __frcp_rn(l1);
    int t0 = qt*128 + qr0 + (lane >> 2);
    long long base0 = ((long long)b*T_ + t0)*D_ + h*HD_;
    long long base1 = base0 + 8LL*D_;
    #pragma unroll
    for (int j=0;j<16;j++){
        int col = j*8 + (lane & 3)*2;
        *reinterpret_cast<uint32_t*>(Ob + base0 + col) = pack_bf16x2(o[j][0]*il0, o[j][1]*il0);
        *reinterpret_cast<uint32_t*>(Ob + base1 + col) = pack_bf16x2(o[j][2]*il1, o[j][3]*il1);
    }
}

// ---------------- elementwise / reduction kernels ----------------

__global__ void cvt_kernel(const float* __restrict__ s, __nv_bfloat16* __restrict__ d, int n4){
    for (int i = blockIdx.x*blockDim.x + threadIdx.x; i < n4; i += gridDim.x*blockDim.x){
        float4 v = reinterpret_cast<const float4*>(s)[i];
        __nv_bfloat162* o = reinterpret_cast<__nv_bfloat162*>(d) + (long long)i*2;
        o[0] = __floats2bfloat162_rn(v.x, v.y);
        o[1] = __floats2bfloat162_rn(v.z, v.w);
    }
}

__global__ void __launch_bounds__(256) router_kernel(const float* __restrict__ x,
                                                     const float* __restrict__ wr){
    int row = blockIdx.x*8 + (threadIdx.x >> 5);
    int lane = threadIdx.x & 31;
    const float* xr = x + (long long)row * D_;
    float s = 0.f;
    #pragma unroll 8
    for (int i = lane; i < D_; i += 32) s += xr[i] * wr[i];
    #pragma unroll
    for (int o=16;o;o>>=1) s += __shfl_xor_sync(0xffffffffu, s, o);
    if (!lane) g_logits[row] = s;
}

__global__ void __launch_bounds__(1024) topk_kernel(){
    __shared__ float sv[S_];
    __shared__ int   scn[1024];
    __shared__ float selv[T_];
    __shared__ float red[1024];
    int b = blockIdx.x, tid = threadIdx.x;
    for (int i = tid; i < S_; i += 1024) sv[i] = g_logits[b*S_ + i];
    __syncthreads();
    int base_i = tid*4;
    float v[4]; int rank[4] = {0,0,0,0};
    #pragma unroll
    for (int e=0;e<4;e++) v[e] = sv[base_i+e];
    for (int j=0;j<S_;j++){
        float vj = sv[j];
        #pragma unroll
        for (int e=0;e<4;e++)
            rank[e] += (vj > v[e]) || (vj == v[e] && j < base_i+e);
    }
    int flag[4]; int cnt = 0;
    #pragma unroll
    for (int e=0;e<4;e++){ flag[e] = rank[e] < T_; cnt += flag[e]; }
    scn[tid] = cnt; __syncthreads();
    for (int off=1; off<1024; off<<=1){
        int t = 0;
        if (tid >= off) t = scn[tid-off];
        __syncthreads();
        scn[tid] += t;
        __syncthreads();
    }
    int pos = scn[tid] - cnt;
    #pragma unroll
    for (int e=0;e<4;e++){
        int i = base_i + e;
        int p = -1;
        if (flag[e]){ p = pos++; g_sel[b*T_+p] = i; selv[p] = v[e]; }
        g_pos[b*S_ + i] = p;
    }
    __syncthreads();
    float sval = selv[tid];
    red[tid] = sval; __syncthreads();
    for (int off=512; off; off>>=1){ if (tid < off) red[tid] = fmaxf(red[tid], red[tid+off]); __syncthreads(); }
    float mx = red[0]; __syncthreads();
    float ex = __expf(sval - mx);
    red[tid] = ex; __syncthreads();
    for (int off=512; off; off>>=1){ if (tid < off) red[tid] += red[tid+off]; __syncthreads(); }
    g_rw[b*T_ + tid] = ex / red[0];
}

__device__ __forceinline__ float block_sum_256(float v, float* sh){
    #pragma unroll
    for (int o=16;o;o>>=1) v += __shfl_xor_sync(0xffffffffu, v, o);
    if ((threadIdx.x & 31) == 0) sh[threadIdx.x >> 5] = v;
    __syncthreads();
    if (threadIdx.x == 0){ float t=0; for (int w=0;w<8;w++) t += sh[w]; sh[0] = t; }
    __syncthreads();
    float r = sh[0];
    __syncthreads();
    return r;
}

__global__ void __launch_bounds__(256) gather_rms_kernel(const float* __restrict__ x,
                                                         const float* __restrict__ g1){
    __shared__ float sh[8];
    int bt = blockIdx.x;
    int b = bt >> 10;
    int s = g_sel[bt];
    const float* xr = x + ((long long)b*S_ + s) * D_;
    float vals[8]; float ss = 0.f;
    #pragma unroll
    for (int e=0;e<8;e++){ float val = xr[threadIdx.x + e*256]; vals[e] = val; ss += val*val; }
    float tot = block_sum_256(ss, sh);
    float inv = rsqrtf(tot / D_ + 1e-6f);
    long long base = (long long)bt * D_;
    #pragma unroll
    for (int e=0;e<8;e++){
        int d = threadIdx.x + e*256;
        g_fx[base+d] = vals[e];
        g_h[base+d]  = __float2bfloat16(vals[e] * inv * g1[d]);
    }
}

__global__ void __launch_bounds__(128) rope_pack_kernel(const float* __restrict__ f){
    int idx = blockIdx.x;
    int t  = idx & (T_-1);
    int bh = idx >> 10;
    int h  = bh & (H_-1);
    int b  = bh >> 4;
    int d  = threadIdx.x;
    long long src = ((long long)(b*T_ + t)) * D_ + h*HD_;
    long long dst = ((long long)(b*H_ + h) * T_ + t) * HD_ + d;
    float qv = g_q[src+d], kv = g_k[src+d], vv = g_v[src+d];
    float qo, ko;
    if (d < 64){
        float c = f[(t*64 + d)*2], sn = f[(t*64 + d)*2 + 1];
        qo = qv*c - g_q[src+d+64]*sn;
        ko = kv*c - g_k[src+d+64]*sn;
    } else {
        int j = d - 64;
        float c = f[(t*64 + j)*2], sn = f[(t*64 + j)*2 + 1];
        qo = g_q[src+j]*sn + qv*c;
        ko = g_k[src+j]*sn + kv*c;
    }
    g_qb[dst] = __float2bfloat16(qo);
    g_kb[dst] = __float2bfloat16(ko);
    g_vb[dst] = __float2bfloat16(vv);
}

__global__ void __launch_bounds__(256) resid_rms_kernel(const float* __restrict__ g2){
    __shared__ float sh[8];
    long long base = (long long)blockIdx.x * D_;
    float vals[8]; float ss = 0.f;
    #pragma unroll
    for (int e=0;e<8;e++){
        int d = threadIdx.x + e*256;
        float val = g_fx[base+d] + g_y[base+d];
        vals[e] = val; ss += val*val;
    }
    float tot = block_sum_256(ss, sh);
    float inv = rsqrtf(tot / D_ + 1e-6f);
    #pragma unroll
    for (int e=0;e<8;e++){
        int d = threadIdx.x + e*256;
        g_x1[base+d] = vals[e];
        g_h2[base+d] = __float2bfloat16(vals[e] * inv * g2[d]);
    }
}

__global__ void __launch_bounds__(256) final_kernel(const float* __restrict__ x,
                                                    float* __restrict__ out){
    int bs = blockIdx.x;
    int b = bs >> 12;
    int pos = g_pos[bs];
    long long rb = (long long)bs * D_;
    if (pos < 0){
        #pragma unroll
        for (int e=0;e<2;e++){
            int i = threadIdx.x + e*256;
            reinterpret_cast<float4*>(out + rb)[i] =
                reinterpret_cast<const float4*>(x + rb)[i];
        }
    } else {
        float w = g_rw[b*T_ + pos];
        long long ob = ((long long)b*T_ + pos) * D_;
        #pragma unroll
        for (int e=0;e<8;e++){
            int d = threadIdx.x + e*256;
            out[rb+d] = x[rb+d] + w * (g_x1[ob+d] + g_y[ob+d]);
        }
    }
}

// ---------------- host orchestration ----------------
#define GETP(sym_) ([&]{ void* p_ = nullptr; cudaGetSymbolAddress(&p_, sym_); return p_; }())

extern "C" void kernel_launch(void* const* d_in, const int* in_sizes, int n_in,
                              void* d_out, int out_size)
{
    const float* x     = (const float*)d_in[0];
    const float* freqs = (const float*)d_in[2];
    const float* wr    = (const float*)d_in[3];
    const float* g1    = (const float*)d_in[4];
    const float* wq    = (const float*)d_in[5];
    const float* wk    = (const float*)d_in[6];
    const float* wv    = (const float*)d_in[7];
    const float* wo    = (const float*)d_in[8];
    const float* g2    = (const float*)d_in[9];
    const float* w1    = (const float*)d_in[10];
    const float* w3    = (const float*)d_in[11];
    const float* w2    = (const float*)d_in[12];
    float* out = (float*)d_out;

    static bool attr_set = false;
    if (!attr_set){
        cudaFuncSetAttribute(gemm3<0,0>, cudaFuncAttributeMaxDynamicSharedMemorySize, GEMM_SMEM);
        cudaFuncSetAttribute(gemm3<0,1>, cudaFuncAttributeMaxDynamicSharedMemorySize, GEMM_SMEM);
        cudaFuncSetAttribute(flash_kernel, cudaFuncAttributeMaxDynamicSharedMemorySize, FA_SMEM);
        attr_set = true;
    }

    __nv_bfloat16* p_wq = (__nv_bfloat16*)GETP(g_wq_b);
    __nv_bfloat16* p_wk = (__nv_bfloat16*)GETP(g_wk_b);
    __nv_bfloat16* p_wv = (__nv_bfloat16*)GETP(g_wv_b);
    __nv_bfloat16* p_wo = (__nv_bfloat16*)GETP(g_wo_b);
    __nv_bfloat16* p_w1 = (__nv_bfloat16*)GETP(g_w1_b);
    __nv_bfloat16* p_w3 = (__nv_bfloat16*)GETP(g_w3_b);
    __nv_bfloat16* p_w2 = (__nv_bfloat16*)GETP(g_w2_b);
    __nv_bfloat16* p_h  = (__nv_bfloat16*)GETP(g_h);
    __nv_bfloat16* p_qb = (__nv_bfloat16*)GETP(g_qb);
    __nv_bfloat16* p_kb = (__nv_bfloat16*)GETP(g_kb);
    __nv_bfloat16* p_vb = (__nv_bfloat16*)GETP(g_vb);
    __nv_bfloat16* p_ob = (__nv_bfloat16*)GETP(g_ob);
    __nv_bfloat16* p_h2 = (__nv_bfloat16*)GETP(g_h2);
    __nv_bfloat16* p_ac = (__nv_bfloat16*)GETP(g_act);
    float* p_q  = (float*)GETP(g_q);
    float* p_k  = (float*)GETP(g_k);
    float* p_v  = (float*)GETP(g_v);
    float* p_u  = (float*)GETP(g_u);
    float* p_y  = (float*)GETP(g_y);

    // 1) weight conversions fp32 -> bf16
    cvt_kernel<<<2048,256>>>(wq, p_wq, D_*D_/4);
    cvt_kernel<<<2048,256>>>(wk, p_wk, D_*D_/4);
    cvt_kernel<<<2048,256>>>(wv, p_wv, D_*D_/4);
    cvt_kernel<<<2048,256>>>(wo, p_wo, D_*D_/4);
    cvt_kernel<<<4096,256>>>(w1, p_w1, D_*F_/4);
    cvt_kernel<<<4096,256>>>(w3, p_w3, D_*F_/4);
    cvt_kernel<<<4096,256>>>(w2, p_w2, F_*D_/4);

    // 2) router + exact top-k + softmax weights
    router_kernel<<<B_*S_/8, 256>>>(x, wr);
    topk_kernel<<<B_, 1024>>>();

    // 3) gather + rmsnorm1
    gather_rms_kernel<<<M_, 256>>>(x, g1);

    // 4) QKV GEMMs
    gemm3<0,0><<<dim3(D_/BN, M_/BM, 1), 256, GEMM_SMEM>>>(p_h, p_wq, p_q, D_, D_, D_, D_, 0,0,0, nullptr, nullptr);
    gemm3<0,0><<<dim3(D_/BN, M_/BM, 1), 256, GEMM_SMEM>>>(p_h, p_wk, p_k, D_, D_, D_, D_, 0,0,0, nullptr, nullptr);
    gemm3<0,0><<<dim3(D_/BN, M_/BM, 1), 256, GEMM_SMEM>>>(p_h, p_wv, p_v, D_, D_, D_, D_, 0,0,0, nullptr, nullptr);

    // 5) RoPE + pack to [b,h,t,hd] bf16
    rope_pack_kernel<<<B_*H_*T_, 128>>>(freqs);

    // 6-8) fused flash attention -> g_ob [b,t,d] bf16
    flash_kernel<<<dim3(T_/128, B_*H_), 256, FA_SMEM>>>(p_qb, p_kb, p_vb, p_ob);

    // 9) attn projection
    gemm3<0,0><<<dim3(D_/BN, M_/BM, 1), 256, GEMM_SMEM>>>(p_ob, p_wo, p_y, D_, D_, D_, D_, 0,0,0, nullptr, nullptr);

    // 10) residual + rmsnorm2
    resid_rms_kernel<<<M_, 256>>>(g2);

    // 11) FFN: u = h2@w1 ; act = silu(u) * (h2@w3) fused ; y = act@w2
    gemm3<0,0><<<dim3(F_/BN, M_/BM, 1), 256, GEMM_SMEM>>>(p_h2, p_w1, p_u, D_, D_, F_, F_, 0,0,0, nullptr, nullptr);
    gemm3<0,1><<<dim3(F_/BN, M_/BM, 1), 256, GEMM_SMEM>>>(p_h2, p_w3, p_u, D_, D_, F_, F_, 0,0,0, p_u, p_ac);
    gemm3<0,0><<<dim3(D_/BN, M_/BM, 1), 256, GEMM_SMEM>>>(p_ac, p_w2, p_y, F_, F_, D_, D_, 0,0,0, nullptr, nullptr);

    // 12) final scatter-add
    final_kernel<<<B_*S_, 256>>>(x, out);
}

// round 6
// speedup vs baseline: 1.8786x; 1.0162x over previous
#include <cuda_runtime.h>
#include <cuda_bf16.h>
#include <cstdint>

// Problem dims
#define B_  4
#define S_  4096
#define D_  2048
#define T_  1024
#define H_  16
#define HD_ 128
#define F_  8192
#define M_  (B_*T_)

// ---------------- device scratch ----------------
#define DEVBUF(type, name, count) __device__ __align__(256) type name[count]

DEVBUF(__nv_bfloat16, g_wqkv, 3LL*D_*D_);   // packed [wq|wk|wv]
DEVBUF(__nv_bfloat16, g_wo_b, D_*D_);
DEVBUF(__nv_bfloat16, g_w1_b, D_*F_);
DEVBUF(__nv_bfloat16, g_w3_b, D_*F_);
DEVBUF(__nv_bfloat16, g_w2_b, F_*D_);

DEVBUF(float, g_logits, B_*S_);
DEVBUF(int,   g_sel,    B_*T_);
DEVBUF(int,   g_pos,    B_*S_);
DEVBUF(float, g_rw,     B_*T_);

DEVBUF(float,         g_fx,  M_*D_);
DEVBUF(__nv_bfloat16, g_h,   M_*D_);
DEVBUF(__nv_bfloat16, g_qkv, 3LL*M_*D_);    // packed q|k|v bf16
DEVBUF(__nv_bfloat16, g_qb,  M_*D_);        // [b,h,t,hd]
DEVBUF(__nv_bfloat16, g_kb,  M_*D_);
DEVBUF(__nv_bfloat16, g_vb,  M_*D_);
DEVBUF(__nv_bfloat16, g_ob,  M_*D_);        // attn out [b,t,d] bf16
DEVBUF(float,         g_x1,  M_*D_);        // fx + attn proj
DEVBUF(__nv_bfloat16, g_h2,  M_*D_);
DEVBUF(__nv_bfloat16, g_u,   M_*F_);        // bf16 u
DEVBUF(__nv_bfloat16, g_act, M_*F_);
DEVBUF(float,         g_y,   M_*D_);        // x1 + ffn

// ---------------- PTX helpers ----------------
__device__ __forceinline__ uint32_t smem_u32(const void* p){
    uint32_t a;
    asm("{ .reg .u64 t; cvta.to.shared.u64 t, %1; cvt.u32.u64 %0, t; }" : "=r"(a) : "l"(p));
    return a;
}
__device__ __forceinline__ void cpasync16(uint32_t dst, const void* src){
    asm volatile("cp.async.cg.shared.global [%0], [%1], 16;" :: "r"(dst), "l"(src));
}
__device__ __forceinline__ void ldsm_x4(uint32_t* r, uint32_t addr){
    asm volatile("ldmatrix.sync.aligned.m8n8.x4.shared.b16 {%0,%1,%2,%3}, [%4];"
        : "=r"(r[0]), "=r"(r[1]), "=r"(r[2]), "=r"(r[3]) : "r"(addr));
}
__device__ __forceinline__ void ldsm_x4_t(uint32_t* r, uint32_t addr){
    asm volatile("ldmatrix.sync.aligned.m8n8.x4.trans.shared.b16 {%0,%1,%2,%3}, [%4];"
        : "=r"(r[0]), "=r"(r[1]), "=r"(r[2]), "=r"(r[3]) : "r"(addr));
}
__device__ __forceinline__ void mma16816(float* c, const uint32_t* a, uint32_t b0, uint32_t b1){
    asm volatile("mma.sync.aligned.m16n8k16.row.col.f32.bf16.bf16.f32 "
        "{%0,%1,%2,%3}, {%4,%5,%6,%7}, {%8,%9}, {%0,%1,%2,%3};"
        : "+f"(c[0]), "+f"(c[1]), "+f"(c[2]), "+f"(c[3])
        : "r"(a[0]), "r"(a[1]), "r"(a[2]), "r"(a[3]), "r"(b0), "r"(b1));
}
__device__ __forceinline__ uint32_t pack_bf16x2(float lo, float hi){
    __nv_bfloat162 v = __floats2bfloat162_rn(lo, hi);
    return *reinterpret_cast<uint32_t*>(&v);
}

// ---------------- raw mma.sync GEMM ----------------
// C[M,N] fp32 = A[M,K](row) * B[K,N](row).
// EPI=0: fp32 store to C
// EPI=1: silu(Ubf[r,c]) * acc -> bf16 store to Obf   (Ubf bf16)
// EPI=2: bf16 store to Obf
// EPI=3: acc + Rf[r,c] -> fp32 store to C            (Rf fp32)

#define BM 128
#define BN 128
#define BK 64
#define STAGE_B 32768
#define GEMM_SMEM (3*STAGE_B)

__device__ __forceinline__ void ldA_128x64(const __nv_bfloat16* g, int ld, uint32_t sbase, int tid){
    #pragma unroll
    for (int i = 0; i < 4; i++){
        int ch = tid + i*256;
        int r = ch >> 3, c = ch & 7;
        cpasync16(sbase + r*128 + (((c ^ (r & 7))) << 4),
                  (const char*)(g + (long long)r*ld) + c*16);
    }
}
__device__ __forceinline__ void ldB_64x128(const __nv_bfloat16* g, int ld, uint32_t sbase, int tid){
    #pragma unroll
    for (int i = 0; i < 4; i++){
        int ch = tid + i*256;
        int r = ch >> 4, c = ch & 15;
        int half = c >> 3, c8 = c & 7;
        cpasync16(sbase + r*256 + half*128 + ((c8 ^ (r & 7)) << 4),
                  (const char*)(g + (long long)r*ld) + c*16);
    }
}

template<int EPI>
__global__ void __launch_bounds__(256, 2) gemm3(
    const __nv_bfloat16* __restrict__ A, const __nv_bfloat16* __restrict__ Bm,
    float* __restrict__ C, int K, int lda, int ldb, int ldc,
    long long sA, long long sB, long long sC,
    const void* __restrict__ Uv, __nv_bfloat16* __restrict__ Obf)
{
    extern __shared__ char smem[];
    uint32_t sb = smem_u32(smem);
    int tid = threadIdx.x, warp = tid >> 5, lane = tid & 31;
    int z = blockIdx.z;
    const __nv_bfloat16* Ab = A + (long long)z*sA + (long long)blockIdx.y*BM*lda;
    const __nv_bfloat16* Bb = Bm + (long long)z*sB;
    float* Cb = C ? C + (long long)z*sC : nullptr;
    __nv_bfloat16* Ob = Obf ? Obf + (long long)z*sC : nullptr;
    const int bn = blockIdx.x*BN;

    int wm = (warp & 3) * 32;
    int wn = (warp >> 2) * 64;

    float acc[2][8][4];
    #pragma unroll
    for (int i=0;i<2;i++)
        #pragma unroll
        for (int j=0;j<8;j++)
            #pragma unroll
            for (int e=0;e<4;e++) acc[i][j][e] = 0.f;

    const int NS = K >> 6;

    auto load_stage = [&](int s){
        uint32_t base = sb + (s % 3)*STAGE_B;
        int k0 = s*BK;
        ldA_128x64(Ab + k0, lda, base, tid);
        ldB_64x128(Bb + (long long)k0*ldb + bn, ldb, base + 16384, tid);
        asm volatile("cp.async.commit_group;" ::: "memory");
    };

    load_stage(0);
    if (NS > 1) load_stage(1);

    int a_row_lo = wm + ((lane >> 3) & 1)*8 + (lane & 7);
    int a_kq     = (lane >> 4) * 8;
    int b0_krow  = ((lane >> 3) & 1)*8 + (lane & 7);
    int b0_ncol  = wn + (lane >> 4)*8;

    for (int s = 0; s < NS; s++){
        if (s + 1 < NS) asm volatile("cp.async.wait_group 1;" ::: "memory");
        else            asm volatile("cp.async.wait_group 0;" ::: "memory");
        __syncthreads();

        if (s + 2 < NS) load_stage(s + 2);

        uint32_t Abase = sb + (s % 3)*STAGE_B;
        uint32_t Bbase = Abase + 16384;

        #pragma unroll
        for (int kk = 0; kk < BK; kk += 16){
            uint32_t af[2][4];
            #pragma unroll
            for (int ii = 0; ii < 2; ii++){
                int mrow = a_row_lo + ii*16;
                int kb = kk + a_kq;
                ldsm_x4(af[ii], Abase + mrow*128 + ((((kb >> 3) ^ (mrow & 7))) << 4));
            }
            uint32_t bfm[4][4];
            #pragma unroll
            for (int jj = 0; jj < 4; jj++){
                int krow = kk + b0_krow;
                int ncol = b0_ncol + jj*16;
                ldsm_x4_t(bfm[jj], Bbase + krow*256 + ((ncol >> 6) & 1)*128
                                 + ((((ncol >> 3) & 7) ^ (krow & 7)) << 4));
            }
            #pragma unroll
            for (int ii = 0; ii < 2; ii++)
                #pragma unroll
                for (int jj = 0; jj < 4; jj++){
                    mma16816(acc[ii][2*jj],   af[ii], bfm[jj][0], bfm[jj][1]);
                    mma16816(acc[ii][2*jj+1], af[ii], bfm[jj][2], bfm[jj][3]);
                }
        }
        __syncthreads();
    }

    #pragma unroll
    for (int ii = 0; ii < 2; ii++){
        int r0 = blockIdx.y*BM + wm + ii*16 + (lane >> 2);
        #pragma unroll
        for (int j8 = 0; j8 < 8; j8++){
            int c0 = bn + wn + j8*8 + (lane & 3)*2;
            long long i0 = (long long)r0*ldc + c0;
            long long i1 = i0 + 8*(long long)ldc;
            if (EPI == 0){
                *reinterpret_cast<float2*>(Cb + i0) = make_float2(acc[ii][j8][0], acc[ii][j8][1]);
                *reinterpret_cast<float2*>(Cb + i1) = make_float2(acc[ii][j8][2], acc[ii][j8][3]);
            } else if (EPI == 1){
                const __nv_bfloat16* Ub = (const __nv_bfloat16*)Uv;
                __nv_bfloat162 u0 = *reinterpret_cast<const __nv_bfloat162*>(Ub + i0);
                __nv_bfloat162 u1 = *reinterpret_cast<const __nv_bfloat162*>(Ub + i1);
                float ux = __bfloat162float(u0.x), uy = __bfloat162float(u0.y);
                float uz = __bfloat162float(u1.x), uw = __bfloat162float(u1.y);
                float s0 = __fdividef(ux, 1.f + __expf(-ux)) * acc[ii][j8][0];
                float s1 = __fdividef(uy, 1.f + __expf(-uy)) * acc[ii][j8][1];
                float s2 = __fdividef(uz, 1.f + __expf(-uz)) * acc[ii][j8][2];
                float s3 = __fdividef(uw, 1.f + __expf(-uw)) * acc[ii][j8][3];
                *reinterpret_cast<uint32_t*>(Ob + i0) = pack_bf16x2(s0, s1);
                *reinterpret_cast<uint32_t*>(Ob + i1) = pack_bf16x2(s2, s3);
            } else if (EPI == 2){
                *reinterpret_cast<uint32_t*>(Ob + i0) = pack_bf16x2(acc[ii][j8][0], acc[ii][j8][1]);
                *reinterpret_cast<uint32_t*>(Ob + i1) = pack_bf16x2(acc[ii][j8][2], acc[ii][j8][3]);
            } else {
                const float* Rf = (const float*)Uv;
                float2 r0v = *reinterpret_cast<const float2*>(Rf + i0);
                float2 r1v = *reinterpret_cast<const float2*>(Rf + i1);
                *reinterpret_cast<float2*>(Cb + i0) = make_float2(acc[ii][j8][0] + r0v.x, acc[ii][j8][1] + r0v.y);
                *reinterpret_cast<float2*>(Cb + i1) = make_float2(acc[ii][j8][2] + r1v.x, acc[ii][j8][3] + r1v.y);
            }
        }
    }
}

// ---------------- fused flash attention ----------------
#define FA_STAGE 32768
#define FA_SMEM (32768 + 3*FA_STAGE)

__global__ void __launch_bounds__(256, 1) flash_kernel(
    const __nv_bfloat16* __restrict__ Q, const __nv_bfloat16* __restrict__ K,
    const __nv_bfloat16* __restrict__ V, __nv_bfloat16* __restrict__ Ob)
{
    extern __shared__ char smem[];
    uint32_t sq = smem_u32(smem);
    int tid = threadIdx.x, warp = tid >> 5, lane = tid & 31;
    int qt = blockIdx.x;
    int bh = blockIdx.y;
    int h = bh & (H_-1), b = bh >> 4;
    const __nv_bfloat16* Qb = Q + ((long long)bh*T_ + qt*128)*HD_;
    const __nv_bfloat16* Kb = K + (long long)bh*T_*HD_;
    const __nv_bfloat16* Vb = V + (long long)bh*T_*HD_;

    #pragma unroll
    for (int i = 0; i < 8; i++){
        int ch = tid + i*256;
        int r = ch >> 4, c = ch & 15;
        cpasync16(sq + r*256 + (c >> 3)*128 + (((c & 7) ^ (r & 7)) << 4),
                  (const char*)(Qb + (long long)r*HD_) + c*16);
    }
    auto load_kv = [&](int s){
        uint32_t base = sq + 32768 + (s % 3)*FA_STAGE;
        const __nv_bfloat16* Kt = Kb + (long long)s*64*HD_;
        const __nv_bfloat16* Vt = Vb + (long long)s*64*HD_;
        #pragma unroll
        for (int i = 0; i < 4; i++){
            int ch = tid + i*256;
            int r = ch >> 4, c = ch & 15;
            uint32_t off = r*256 + (c >> 3)*128 + (((c & 7) ^ (r & 7)) << 4);
            cpasync16(base + off,         (const char*)(Kt + (long long)r*HD_) + c*16);
            cpasync16(base + 16384 + off, (const char*)(Vt + (long long)r*HD_) + c*16);
        }
        asm volatile("cp.async.commit_group;" ::: "memory");
    };
    load_kv(0);
    load_kv(1);

    const int qr0 = warp*16;
    float o[16][4];
    #pragma unroll
    for (int j=0;j<16;j++)
        #pragma unroll
        for (int e=0;e<4;e++) o[j][e] = 0.f;
    float m0 = -1e30f, m1 = -1e30f, l0 = 0.f, l1 = 0.f;
    const float sc = 0.08838834764831845f;

    int a_row  = qr0 + ((lane >> 3) & 1)*8 + (lane & 7);
    int a_kq   = (lane >> 4) * 8;
    int b_row  = (lane >> 4)*8 + (lane & 7);
    int b_kq   = ((lane >> 3) & 1) * 8;
    int v_krow = ((lane >> 3) & 1)*8 + (lane & 7);
    int v_ncol = (lane >> 4) * 8;

    for (int s = 0; s < 16; s++){
        if (s + 1 < 16) asm volatile("cp.async.wait_group 1;" ::: "memory");
        else            asm volatile("cp.async.wait_group 0;" ::: "memory");
        __syncthreads();
        if (s + 2 < 16) load_kv(s + 2);

        uint32_t Kbase = sq + 32768 + (s % 3)*FA_STAGE;
        uint32_t Vbase = Kbase + 16384;

        float sv[8][4];
        #pragma unroll
        for (int j=0;j<8;j++)
            #pragma unroll
            for (int e=0;e<4;e++) sv[j][e] = 0.f;

        #pragma unroll
        for (int kk = 0; kk < 8; kk++){
            uint32_t af[4];
            int cA = (kk*16 + a_kq) >> 3;
            ldsm_x4(af, sq + a_row*256 + (cA >> 3)*128 + (((cA & 7) ^ (a_row & 7)) << 4));
            #pragma unroll
            for (int jj = 0; jj < 4; jj++){
                uint32_t bfm[4];
                int nrow = jj*16 + b_row;
                int cB = (kk*16 + b_kq) >> 3;
                ldsm_x4(bfm, Kbase + nrow*256 + (cB >> 3)*128 + (((cB & 7) ^ (nrow & 7)) << 4));
                mma16816(sv[2*jj],   af, bfm[0], bfm[1]);
                mma16816(sv[2*jj+1], af, bfm[2], bfm[3]);
            }
        }

        float rm0 = -1e30f, rm1 = -1e30f;
        #pragma unroll
        for (int j=0;j<8;j++){
            sv[j][0] *= sc; sv[j][1] *= sc; sv[j][2] *= sc; sv[j][3] *= sc;
            rm0 = fmaxf(rm0, fmaxf(sv[j][0], sv[j][1]));
            rm1 = fmaxf(rm1, fmaxf(sv[j][2], sv[j][3]));
        }
        rm0 = fmaxf(rm0, __shfl_xor_sync(0xffffffffu, rm0, 1));
        rm0 = fmaxf(rm0, __shfl_xor_sync(0xffffffffu, rm0, 2));
        rm1 = fmaxf(rm1, __shfl_xor_sync(0xffffffffu, rm1, 1));
        rm1 = fmaxf(rm1, __shfl_xor_sync(0xffffffffu, rm1, 2));
        float mn0 = fmaxf(m0, rm0), mn1 = fmaxf(m1, rm1);
        float rs0 = 0.f, rs1 = 0.f;
        #pragma unroll
        for (int j=0;j<8;j++){
            sv[j][0] = __expf(sv[j][0] - mn0);
            sv[j][1] = __expf(sv[j][1] - mn0);
            sv[j][2] = __expf(sv[j][2] - mn1);
            sv[j][3] = __expf(sv[j][3] - mn1);
            rs0 += sv[j][0] + sv[j][1];
            rs1 += sv[j][2] + sv[j][3];
        }
        rs0 += __shfl_xor_sync(0xffffffffu, rs0, 1);
        rs0 += __shfl_xor_sync(0xffffffffu, rs0, 2);
        rs1 += __shfl_xor_sync(0xffffffffu, rs1, 1);
        rs1 += __shfl_xor_sync(0xffffffffu, rs1, 2);
        float c0 = __expf(m0 - mn0), c1 = __expf(m1 - mn1);
        l0 = l0*c0 + rs0;  l1 = l1*c1 + rs1;
        m0 = mn0;  m1 = mn1;
        #pragma unroll
        for (int j=0;j<16;j++){
            o[j][0] *= c0; o[j][1] *= c0; o[j][2] *= c1; o[j][3] *= c1;
        }

        #pragma unroll
        for (int k2 = 0; k2 < 4; k2++){
            uint32_t pa[4];
            pa[0] = pack_bf16x2(sv[2*k2][0],   sv[2*k2][1]);
            pa[1] = pack_bf16x2(sv[2*k2][2],   sv[2*k2][3]);
            pa[2] = pack_bf16x2(sv[2*k2+1][0], sv[2*k2+1][1]);
            pa[3] = pack_bf16x2(sv[2*k2+1][2], sv[2*k2+1][3]);
            int krow = k2*16 + v_krow;
            #pragma unroll
            for (int jj = 0; jj < 8; jj++){
                uint32_t bv[4];
                int ncol = jj*16 + v_ncol;
                ldsm_x4_t(bv, Vbase + krow*256 + ((ncol >> 6) & 1)*128
                              + ((((ncol >> 3) & 7) ^ (krow & 7)) << 4));
                mma16816(o[2*jj],   pa, bv[0], bv[1]);
                mma16816(o[2*jj+1], pa, bv[2], bv[3]);
            }
        }
        __syncthreads();
    }

    float il0 = __frcp_rn(l0), il1 = __frcp_rn(l1);
    int t0 = qt*128 + qr0 + (lane >> 2);
    long long base0 = ((long long)b*T_ + t0)*D_ + h*HD_;
    long long base1 = base0 + 8LL*D_;
    #pragma unroll
    for (int j=0;j<16;j++){
        int col = j*8 + (lane & 3)*2;
        *reinterpret_cast<uint32_t*>(Ob + base0 + col) = pack_bf16x2(o[j][0]*il0, o[j][1]*il0);
        *reinterpret_cast<uint32_t*>(Ob + base1 + col) = pack_bf16x2(o[j][2]*il1, o[j][3]*il1);
    }
}

// ---------------- elementwise / reduction kernels ----------------

__global__ void cvt_kernel(const float* __restrict__ s, __nv_bfloat16* __restrict__ d, int n4){
    for (int i = blockIdx.x*blockDim.x + threadIdx.x; i < n4; i += gridDim.x*blockDim.x){
        float4 v = reinterpret_cast<const float4*>(s)[i];
        __nv_bfloat162* o = reinterpret_cast<__nv_bfloat162*>(d) + (long long)i*2;
        o[0] = __floats2bfloat162_rn(v.x, v.y);
        o[1] = __floats2bfloat162_rn(v.z, v.w);
    }
}

__global__ void __launch_bounds__(256) router_kernel(const float* __restrict__ x,
                                                     const float* __restrict__ wr){
    int row = blockIdx.x*8 + (threadIdx.x >> 5);
    int lane = threadIdx.x & 31;
    const float* xr = x + (long long)row * D_;
    float s = 0.f;
    #pragma unroll 8
    for (int i = lane; i < D_; i += 32) s += xr[i] * wr[i];
    #pragma unroll
    for (int o=16;o;o>>=1) s += __shfl_xor_sync(0xffffffffu, s, o);
    if (!lane) g_logits[row] = s;
}

__global__ void __launch_bounds__(1024) topk_kernel(){
    __shared__ float sv[S_];
    __shared__ int   scn[1024];
    __shared__ float selv[T_];
    __shared__ float red[1024];
    int b = blockIdx.x, tid = threadIdx.x;
    for (int i = tid; i < S_; i += 1024) sv[i] = g_logits[b*S_ + i];
    __syncthreads();
    int base_i = tid*4;
    float v[4]; int rank[4] = {0,0,0,0};
    #pragma unroll
    for (int e=0;e<4;e++) v[e] = sv[base_i+e];
    for (int j=0;j<S_;j++){
        float vj = sv[j];
        #pragma unroll
        for (int e=0;e<4;e++)
            rank[e] += (vj > v[e]) || (vj == v[e] && j < base_i+e);
    }
    int flag[4]; int cnt = 0;
    #pragma unroll
    for (int e=0;e<4;e++){ flag[e] = rank[e] < T_; cnt += flag[e]; }
    scn[tid] = cnt; __syncthreads();
    for (int off=1; off<1024; off<<=1){
        int t = 0;
        if (tid >= off) t = scn[tid-off];
        __syncthreads();
        scn[tid] += t;
        __syncthreads();
    }
    int pos = scn[tid] - cnt;
    #pragma unroll
    for (int e=0;e<4;e++){
        int i = base_i + e;
        int p = -1;
        if (flag[e]){ p = pos++; g_sel[b*T_+p] = i; selv[p] = v[e]; }
        g_pos[b*S_ + i] = p;
    }
    __syncthreads();
    float sval = selv[tid];
    red[tid] = sval; __syncthreads();
    for (int off=512; off; off>>=1){ if (tid < off) red[tid] = fmaxf(red[tid], red[tid+off]); __syncthreads(); }
    float mx = red[0]; __syncthreads();
    float ex = __expf(sval - mx);
    red[tid] = ex; __syncthreads();
    for (int off=512; off; off>>=1){ if (tid < off) red[tid] += red[tid+off]; __syncthreads(); }
    g_rw[b*T_ + tid] = ex / red[0];
}

__device__ __forceinline__ float block_sum_256(float v, float* sh){
    #pragma unroll
    for (int o=16;o;o>>=1) v += __shfl_xor_sync(0xffffffffu, v, o);
    if ((threadIdx.x & 31) == 0) sh[threadIdx.x >> 5] = v;
    __syncthreads();
    if (threadIdx.x == 0){ float t=0; for (int w=0;w<8;w++) t += sh[w]; sh[0] = t; }
    __syncthreads();
    float r = sh[0];
    __syncthreads();
    return r;
}

__global__ void __launch_bounds__(256) gather_rms_kernel(const float* __restrict__ x,
                                                         const float* __restrict__ g1){
    __shared__ float sh[8];
    int bt = blockIdx.x;
    int b = bt >> 10;
    int s = g_sel[bt];
    const float* xr = x + ((long long)b*S_ + s) * D_;
    float vals[8]; float ss = 0.f;
    #pragma unroll
    for (int e=0;e<8;e++){ float val = xr[threadIdx.x + e*256]; vals[e] = val; ss += val*val; }
    float tot = block_sum_256(ss, sh);
    float inv = rsqrtf(tot / D_ + 1e-6f);
    long long base = (long long)bt * D_;
    #pragma unroll
    for (int e=0;e<8;e++){
        int d = threadIdx.x + e*256;
        g_fx[base+d] = vals[e];
        g_h[base+d]  = __float2bfloat16(vals[e] * inv * g1[d]);
    }
}

__global__ void __launch_bounds__(128) rope_pack_kernel(const float* __restrict__ f){
    int idx = blockIdx.x;
    int t  = idx & (T_-1);
    int bh = idx >> 10;
    int h  = bh & (H_-1);
    int b  = bh >> 4;
    int d  = threadIdx.x;
    long long src = ((long long)(b*T_ + t)) * D_ + h*HD_;
    long long dst = ((long long)(b*H_ + h) * T_ + t) * HD_ + d;
    const __nv_bfloat16* q = g_qkv;
    const __nv_bfloat16* k = g_qkv + (long long)M_*D_;
    const __nv_bfloat16* v = g_qkv + 2LL*M_*D_;
    float qv = __bfloat162float(q[src+d]), kv = __bfloat162float(k[src+d]);
    float qo, ko;
    if (d < 64){
        float c = f[(t*64 + d)*2], sn = f[(t*64 + d)*2 + 1];
        qo = qv*c - __bfloat162float(q[src+d+64])*sn;
        ko = kv*c - __bfloat162float(k[src+d+64])*sn;
    } else {
        int j = d - 64;
        float c = f[(t*64 + j)*2], sn = f[(t*64 + j)*2 + 1];
        qo = __bfloat162float(q[src+j])*sn + qv*c;
        ko = __bfloat162float(k[src+j])*sn + kv*c;
    }
    g_qb[dst] = __float2bfloat16(qo);
    g_kb[dst] = __float2bfloat16(ko);
    g_vb[dst] = v[src+d];
}

__global__ void __launch_bounds__(256) resid_rms_kernel(const float* __restrict__ g2){
    __shared__ float sh[8];
    long long base = (long long)blockIdx.x * D_;
    float vals[8]; float ss = 0.f;
    #pragma unroll
    for (int e=0;e<8;e++){
        int d = threadIdx.x + e*256;
        float val = g_x1[base+d];
        vals[e] = val; ss += val*val;
    }
    float tot = block_sum_256(ss, sh);
    float inv = rsqrtf(tot / D_ + 1e-6f);
    #pragma unroll
    for (int e=0;e<8;e++){
        int d = threadIdx.x + e*256;
        g_h2[base+d] = __float2bfloat16(vals[e] * inv * g2[d]);
    }
}

__global__ void __launch_bounds__(256) final_kernel(const float* __restrict__ x,
                                                    float* __restrict__ out){
    int bs = blockIdx.x;
    int b = bs >> 12;
    int pos = g_pos[bs];
    long long rb = (long long)bs * D_;
    if (pos < 0){
        #pragma unroll
        for (int e=0;e<2;e++){
            int i = threadIdx.x + e*256;
            reinterpret_cast<float4*>(out + rb)[i] =
                reinterpret_cast<const float4*>(x + rb)[i];
        }
    } else {
        float w = g_rw[b*T_ + pos];
        long long ob = ((long long)b*T_ + pos) * D_;
        #pragma unroll
        for (int e=0;e<8;e++){
            int d = threadIdx.x + e*256;
            out[rb+d] = x[rb+d] + w * g_y[ob+d];
        }
    }
}

// ---------------- host orchestration ----------------
#define GETP(sym_) ([&]{ void* p_ = nullptr; cudaGetSymbolAddress(&p_, sym_); return p_; }())

extern "C" void kernel_launch(void* const* d_in, const int* in_sizes, int n_in,
                              void* d_out, int out_size)
{
    const float* x     = (const float*)d_in[0];
    const float* freqs = (const float*)d_in[2];
    const float* wr    = (const float*)d_in[3];
    const float* g1    = (const float*)d_in[4];
    const float* wq    = (const float*)d_in[5];
    const float* wk    = (const float*)d_in[6];
    const float* wv    = (const float*)d_in[7];
    const float* wo    = (const float*)d_in[8];
    const float* g2    = (const float*)d_in[9];
    const float* w1    = (const float*)d_in[10];
    const float* w3    = (const float*)d_in[11];
    const float* w2    = (const float*)d_in[12];
    float* out = (float*)d_out;

    static bool attr_set = false;
    if (!attr_set){
        cudaFuncSetAttribute(gemm3<0>, cudaFuncAttributeMaxDynamicSharedMemorySize, GEMM_SMEM);
        cudaFuncSetAttribute(gemm3<1>, cudaFuncAttributeMaxDynamicSharedMemorySize, GEMM_SMEM);
        cudaFuncSetAttribute(gemm3<2>, cudaFuncAttributeMaxDynamicSharedMemorySize, GEMM_SMEM);
        cudaFuncSetAttribute(gemm3<3>, cudaFuncAttributeMaxDynamicSharedMemorySize, GEMM_SMEM);
        cudaFuncSetAttribute(flash_kernel, cudaFuncAttributeMaxDynamicSharedMemorySize, FA_SMEM);
        attr_set = true;
    }

    __nv_bfloat16* p_wqkv = (__nv_bfloat16*)GETP(g_wqkv);
    __nv_bfloat16* p_wo = (__nv_bfloat16*)GETP(g_wo_b);
    __nv_bfloat16* p_w1 = (__nv_bfloat16*)GETP(g_w1_b);
    __nv_bfloat16* p_w3 = (__nv_bfloat16*)GETP(g_w3_b);
    __nv_bfloat16* p_w2 = (__nv_bfloat16*)GETP(g_w2_b);
    __nv_bfloat16* p_h  = (__nv_bfloat16*)GETP(g_h);
    __nv_bfloat16* p_qkv = (__nv_bfloat16*)GETP(g_qkv);
    __nv_bfloat16* p_qb = (__nv_bfloat16*)GETP(g_qb);
    __nv_bfloat16* p_kb = (__nv_bfloat16*)GETP(g_kb);
    __nv_bfloat16* p_vb = (__nv_bfloat16*)GETP(g_vb);
    __nv_bfloat16* p_ob = (__nv_bfloat16*)GETP(g_ob);
    __nv_bfloat16* p_h2 = (__nv_bfloat16*)GETP(g_h2);
    __nv_bfloat16* p_u  = (__nv_bfloat16*)GETP(g_u);
    __nv_bfloat16* p_ac = (__nv_bfloat16*)GETP(g_act);
    float* p_fx = (float*)GETP(g_fx);
    float* p_x1 = (float*)GETP(g_x1);
    float* p_y  = (float*)GETP(g_y);

    // 1) weight conversions fp32 -> bf16 (wq|wk|wv packed)
    cvt_kernel<<<2048,256>>>(wq, p_wqkv,            D_*D_/4);
    cvt_kernel<<<2048,256>>>(wk, p_wqkv + D_*D_,    D_*D_/4);
    cvt_kernel<<<2048,256>>>(wv, p_wqkv + 2*D_*D_,  D_*D_/4);
    cvt_kernel<<<2048,256>>>(wo, p_wo, D_*D_/4);
    cvt_kernel<<<4096,256>>>(w1, p_w1, D_*F_/4);
    cvt_kernel<<<4096,256>>>(w3, p_w3, D_*F_/4);
    cvt_kernel<<<4096,256>>>(w2, p_w2, F_*D_/4);

    // 2) router + exact top-k + softmax weights
    router_kernel<<<B_*S_/8, 256>>>(x, wr);
    topk_kernel<<<B_, 1024>>>();

    // 3) gather + rmsnorm1
    gather_rms_kernel<<<M_, 256>>>(x, g1);

    // 4) QKV as one z=3 batched GEMM, bf16 out
    gemm3<2><<<dim3(D_/BN, M_/BM, 3), 256, GEMM_SMEM>>>(p_h, p_wqkv, nullptr,
        D_, D_, D_, D_, 0, (long long)D_*D_, (long long)M_*D_, nullptr, p_qkv);

    // 5) RoPE + pack to [b,h,t,hd] bf16
    rope_pack_kernel<<<B_*H_*T_, 128>>>(freqs);

    // 6-8) fused flash attention -> g_ob [b,t,d] bf16
    flash_kernel<<<dim3(T_/128, B_*H_), 256, FA_SMEM>>>(p_qb, p_kb, p_vb, p_ob);

    // 9) attn projection + residual: x1 = fx + ob@wo
    gemm3<3><<<dim3(D_/BN, M_/BM, 1), 256, GEMM_SMEM>>>(p_ob, p_wo, p_x1,
        D_, D_, D_, D_, 0,0,0, p_fx, nullptr);

    // 10) rmsnorm2
    resid_rms_kernel<<<M_, 256>>>(g2);

    // 11) FFN: u = h2@w1 (bf16) ; act = silu(u)*(h2@w3) ; y = x1 + act@w2
    gemm3<2><<<dim3(F_/BN, M_/BM, 1), 256, GEMM_SMEM>>>(p_h2, p_w1, nullptr,
        D_, D_, F_, F_, 0,0,0, nullptr, p_u);
    gemm3<1><<<dim3(F_/BN, M_/BM, 1), 256, GEMM_SMEM>>>(p_h2, p_w3, nullptr,
        D_, D_, F_, F_, 0,0,0, p_u, p_ac);
    gemm3<3><<<dim3(D_/BN, M_/BM, 1), 256, GEMM_SMEM>>>(p_ac, p_w2, p_y,
        F_, F_, D_, D_, 0,0,0, p_x1, nullptr);

    // 12) final scatter-add
    final_kernel<<<B_*S_, 256>>>(x, out);
}